// round 4
// baseline (speedup 1.0000x reference)
#include <cuda_runtime.h>
#include <cuda_bf16.h>
#include <math.h>
#include <stdint.h>

#define N_NODES 50000
#define N_EDGES 800000
#define HH 256
#define NHEADS 4
#define MPAD 50048

// ---------------- scratch ----------------
__device__ float g_h  [(size_t)N_NODES * HH];
__device__ float g_h2 [(size_t)N_NODES * HH];
__device__ float g_el [N_NODES * NHEADS];
__device__ float g_er [N_NODES * NHEADS];
__device__ int   g_rowptr[N_NODES + 1];
__device__ int   g_counts[N_NODES];
__device__ int   g_csr_src[N_EDGES];
__device__ __nv_bfloat16 g_a_hi[(size_t)MPAD * 256];
__device__ __nv_bfloat16 g_a_lo[(size_t)MPAD * 256];
__device__ __nv_bfloat16 g_w_hi[3 * 256 * 256];   // W^T per layer, [n][k]
__device__ __nv_bfloat16 g_w_lo[3 * 256 * 256];

// ---------------- CSR build ----------------
__global__ void zero_counts_k() {
    int i = blockIdx.x * blockDim.x + threadIdx.x;
    if (i < N_NODES) g_counts[i] = 0;
}
__global__ void hist_k(const int* __restrict__ dst, int E) {
    int i = blockIdx.x * blockDim.x + threadIdx.x;
    if (i < E) atomicAdd(&g_counts[dst[i]], 1);
}
__global__ void scan_k() {
    __shared__ int part[1024];
    const int C = (N_NODES + 1023) / 1024;
    int t = threadIdx.x;
    int base = t * C;
    int s = 0;
    for (int i = 0; i < C; i++) { int id = base + i; if (id < N_NODES) s += g_counts[id]; }
    part[t] = s;
    __syncthreads();
    for (int off = 1; off < 1024; off <<= 1) {
        int v = (t >= off) ? part[t - off] : 0;
        __syncthreads();
        part[t] += v;
        __syncthreads();
    }
    int run = (t == 0) ? 0 : part[t - 1];
    for (int i = 0; i < C; i++) {
        int id = base + i;
        if (id < N_NODES) { g_rowptr[id] = run; run += g_counts[id]; }
    }
    if (t == 1023) g_rowptr[N_NODES] = part[1023];
}
__global__ void scatter_k(const int* __restrict__ src, const int* __restrict__ dst, int E) {
    int i = blockIdx.x * blockDim.x + threadIdx.x;
    if (i < E) {
        int d = dst[i];
        int pos = g_rowptr[d] + atomicAdd(&g_counts[d], 1);
        g_csr_src[pos] = src[i];
    }
}

// ---------------- conversions ----------------
__global__ void convert_x_k(const float* __restrict__ x, int total) {
    int i = blockIdx.x * blockDim.x + threadIdx.x;
    if (i >= total) return;
    float a = x[i];
    __nv_bfloat16 hi = __float2bfloat16(a);
    __nv_bfloat16 lo = __float2bfloat16(a - __bfloat162float(hi));
    g_a_hi[i] = hi;
    g_a_lo[i] = lo;
}
__global__ void convert_w_k(const float* __restrict__ W, int K,
                            __nv_bfloat16* __restrict__ oh, __nv_bfloat16* __restrict__ ol) {
    int i = blockIdx.x * blockDim.x + threadIdx.x;
    if (i >= K * 256) return;
    int k = i / 256, n = i % 256;
    float a = W[i];
    __nv_bfloat16 hi = __float2bfloat16(a);
    __nv_bfloat16 lo = __float2bfloat16(a - __bfloat162float(hi));
    oh[(size_t)n * K + k] = hi;
    ol[(size_t)n * K + k] = lo;
}

// ---------------- warp-MMA helpers ----------------
__device__ __forceinline__ void ldsm4(uint32_t (&r)[4], uint32_t addr) {
    asm volatile("ldmatrix.sync.aligned.m8n8.x4.shared.b16 {%0,%1,%2,%3}, [%4];"
                 : "=r"(r[0]), "=r"(r[1]), "=r"(r[2]), "=r"(r[3]) : "r"(addr));
}
__device__ __forceinline__ void mma16816(float (&d)[4], const uint32_t (&a)[4],
                                         uint32_t b0, uint32_t b1) {
    asm volatile(
        "mma.sync.aligned.m16n8k16.row.col.f32.bf16.bf16.f32 "
        "{%0,%1,%2,%3}, {%4,%5,%6,%7}, {%8,%9}, {%0,%1,%2,%3};"
        : "+f"(d[0]), "+f"(d[1]), "+f"(d[2]), "+f"(d[3])
        : "r"(a[0]), "r"(a[1]), "r"(a[2]), "r"(a[3]), "r"(b0), "r"(b1));
}
__device__ __forceinline__ void cp16(uint32_t dst, const void* src, uint32_t n) {
    asm volatile("cp.async.cg.shared.global [%0], [%1], 16, %2;"
                 :: "r"(dst), "l"(src), "r"(n) : "memory");
}
#define CP_COMMIT() asm volatile("cp.async.commit_group;" ::: "memory")
#define CP_WAIT(n)  asm volatile("cp.async.wait_group %0;" :: "n"(n) : "memory")

// ---------------- tensor-core GEMM with cp.async double buffer ----------------
// block tile 128x128, 8 warps (warp_m = wid&3 -> 32 rows, warp_n = wid>>2 -> 64 cols = one head)
#define LDA 80
#define ARR_BYTES (128 * LDA)
#define STAGE_BYTES (4 * ARR_BYTES)   // Ah, Al, Bh, Bl
// dynamic smem total = 2 * STAGE_BYTES = 81920

template <int K>
__global__ void __launch_bounds__(256) gemm_mma_k(
    const __nv_bfloat16* __restrict__ Ah, const __nv_bfloat16* __restrict__ Al,
    const __nv_bfloat16* __restrict__ Bh, const __nv_bfloat16* __restrict__ Bl,
    float* __restrict__ C, const float* __restrict__ alw, const float* __restrict__ arw)
{
    extern __shared__ __align__(16) uint8_t smem[];
    const int t = threadIdx.x;
    const int wid = t >> 5, lane = t & 31;
    const int warp_m = wid & 3, warp_n = wid >> 2;
    const int row0 = blockIdx.y * 128;
    const int nbase = blockIdx.x * 128;
    constexpr int NCHUNK = K / 32;

    float acc[2][8][4];
#pragma unroll
    for (int i = 0; i < 2; i++)
#pragma unroll
        for (int j = 0; j < 8; j++)
#pragma unroll
            for (int q = 0; q < 4; q++) acc[i][j][q] = 0.f;

    const uint32_t sbase = (uint32_t)__cvta_generic_to_shared(smem);

    // cp.async staging mapping: row = t>>1, 32B half = t&1
    const int lrow = t >> 1;
    const int lhalf = (t & 1) * 32;              // byte offset within 64B row payload
    const int arow_real = row0 + lrow;
    const bool aok = arow_real < N_NODES;
    const int arow = aok ? arow_real : (N_NODES - 1);
    const uint32_t asz = aok ? 16u : 0u;
    const int brow = nbase + lrow;
    const uint32_t dOff = (uint32_t)lrow * LDA + (uint32_t)lhalf;

    auto issue = [&](int c, int stage) {
        const int k0 = c * 32;
        const uint32_t sb = sbase + stage * STAGE_BYTES + dOff;
        const char* pa = (const char*)(Ah + (size_t)arow * K + k0) + lhalf;
        const char* pl = (const char*)(Al + (size_t)arow * K + k0) + lhalf;
        const char* pb = (const char*)(Bh + (size_t)brow * K + k0) + lhalf;
        const char* pq = (const char*)(Bl + (size_t)brow * K + k0) + lhalf;
        cp16(sb + 0 * ARR_BYTES +  0, pa +  0, asz);
        cp16(sb + 0 * ARR_BYTES + 16, pa + 16, asz);
        cp16(sb + 1 * ARR_BYTES +  0, pl +  0, asz);
        cp16(sb + 1 * ARR_BYTES + 16, pl + 16, asz);
        cp16(sb + 2 * ARR_BYTES +  0, pb +  0, 16u);
        cp16(sb + 2 * ARR_BYTES + 16, pb + 16, 16u);
        cp16(sb + 3 * ARR_BYTES +  0, pq +  0, 16u);
        cp16(sb + 3 * ARR_BYTES + 16, pq + 16, 16u);
        CP_COMMIT();
    };

    // ldmatrix per-thread offsets
    const uint32_t rowOff = (uint32_t)(lane & 15) * LDA + (uint32_t)((lane >> 4) << 4);
    const uint32_t aOff = (uint32_t)warp_m * 32 * LDA + rowOff;
    const uint32_t bOff = (uint32_t)warp_n * 64 * LDA + rowOff;

    issue(0, 0);

    for (int c = 0; c < NCHUNK; c++) {
        const int stage = c & 1;
        if (c + 1 < NCHUNK) {
            issue(c + 1, stage ^ 1);
            CP_WAIT(1);
        } else {
            CP_WAIT(0);
        }
        __syncthreads();

        const uint32_t uAh = sbase + stage * STAGE_BYTES + 0 * ARR_BYTES;
        const uint32_t uAl = uAh + ARR_BYTES;
        const uint32_t uBh = uAl + ARR_BYTES;
        const uint32_t uBl = uBh + ARR_BYTES;

#pragma unroll
        for (int kk = 0; kk < 2; kk++) {
            const uint32_t kb = kk * 32;
            uint32_t aH[2][4], aL[2][4], bH[4][4], bL[4][4];
#pragma unroll
            for (int mt = 0; mt < 2; mt++) ldsm4(aH[mt], uAh + aOff + mt * 16 * LDA + kb);
#pragma unroll
            for (int p = 0; p < 4; p++) ldsm4(bH[p], uBh + bOff + p * 16 * LDA + kb);
#pragma unroll
            for (int mt = 0; mt < 2; mt++)
#pragma unroll
                for (int p = 0; p < 4; p++) {
                    mma16816(acc[mt][2 * p + 0], aH[mt], bH[p][0], bH[p][2]);
                    mma16816(acc[mt][2 * p + 1], aH[mt], bH[p][1], bH[p][3]);
                }
#pragma unroll
            for (int p = 0; p < 4; p++) ldsm4(bL[p], uBl + bOff + p * 16 * LDA + kb);
#pragma unroll
            for (int mt = 0; mt < 2; mt++)
#pragma unroll
                for (int p = 0; p < 4; p++) {
                    mma16816(acc[mt][2 * p + 0], aH[mt], bL[p][0], bL[p][2]);
                    mma16816(acc[mt][2 * p + 1], aH[mt], bL[p][1], bL[p][3]);
                }
#pragma unroll
            for (int mt = 0; mt < 2; mt++) ldsm4(aL[mt], uAl + aOff + mt * 16 * LDA + kb);
#pragma unroll
            for (int mt = 0; mt < 2; mt++)
#pragma unroll
                for (int p = 0; p < 4; p++) {
                    mma16816(acc[mt][2 * p + 0], aL[mt], bH[p][0], bH[p][2]);
                    mma16816(acc[mt][2 * p + 1], aL[mt], bH[p][1], bH[p][3]);
                }
        }
        __syncthreads();
    }

    // ---- epilogue: write C + fused attention scores (unique writer per row/head) ----
    const int g = lane >> 2;
    const int tig = lane & 3;
    const int head = blockIdx.x * 2 + warp_n;
    const int cihb = tig * 2;

#pragma unroll
    for (int mt = 0; mt < 2; mt++) {
#pragma unroll
        for (int half = 0; half < 2; half++) {
            int grow = row0 + warp_m * 32 + mt * 16 + g + half * 8;
            if (grow >= N_NODES) continue;
            float sl = 0.f, sr = 0.f;
            float* cp = C + (size_t)grow * 256 + nbase + warp_n * 64;
#pragma unroll
            for (int nt = 0; nt < 8; nt++) {
                float c0 = acc[mt][nt][half * 2 + 0];
                float c1 = acc[mt][nt][half * 2 + 1];
                int cih = nt * 8 + cihb;
                *(float2*)(cp + cih) = make_float2(c0, c1);
                sl += c0 * alw[head * 64 + cih] + c1 * alw[head * 64 + cih + 1];
                sr += c0 * arw[head * 64 + cih] + c1 * arw[head * 64 + cih + 1];
            }
            sl += __shfl_xor_sync(0xffffffffu, sl, 1);
            sl += __shfl_xor_sync(0xffffffffu, sl, 2);
            sr += __shfl_xor_sync(0xffffffffu, sr, 1);
            sr += __shfl_xor_sync(0xffffffffu, sr, 2);
            if (tig == 0) {
                g_el[grow * 4 + head] = sl;
                g_er[grow * 4 + head] = sr;
            }
        }
    }
}

// ---------------- fused edge softmax + aggregate + ELU + bf16 split ----------------
__global__ void __launch_bounds__(128) aggregate_k(const float* __restrict__ h,
                                                   float* __restrict__ out, int N) {
    int v = (blockIdx.x * 128 + threadIdx.x) >> 5;
    int lane = threadIdx.x & 31;
    if (v >= N) return;
    int hd = lane >> 3;

    float4 er4 = ((const float4*)g_er)[v];
    float erv = (hd == 0) ? er4.x : (hd == 1) ? er4.y : (hd == 2) ? er4.z : er4.w;

    int r0 = g_rowptr[v];
    int r1 = g_rowptr[v + 1];

    float m = -INFINITY;
    for (int j = r0; j < r1; j++) {
        int s = g_csr_src[j];
        float4 el4 = ((const float4*)g_el)[s];
        float elv = (hd == 0) ? el4.x : (hd == 1) ? el4.y : (hd == 2) ? el4.z : el4.w;
        float e = elv + erv;
        e = (e > 0.f) ? e : 0.2f * e;
        m = fmaxf(m, e);
    }

    float ssum = 0.f;
    float4 acca = make_float4(0.f, 0.f, 0.f, 0.f);
    float4 accb = make_float4(0.f, 0.f, 0.f, 0.f);
    for (int j = r0; j < r1; j++) {
        int s = g_csr_src[j];
        float4 el4 = ((const float4*)g_el)[s];
        float elv = (hd == 0) ? el4.x : (hd == 1) ? el4.y : (hd == 2) ? el4.z : el4.w;
        float e = elv + erv;
        e = (e > 0.f) ? e : 0.2f * e;
        float wgt = __expf(e - m);
        ssum += wgt;
        const float4* hp = (const float4*)(h + (size_t)s * HH + lane * 8);
        float4 ha = hp[0], hb = hp[1];
        acca.x += wgt * ha.x; acca.y += wgt * ha.y;
        acca.z += wgt * ha.z; acca.w += wgt * ha.w;
        accb.x += wgt * hb.x; accb.y += wgt * hb.y;
        accb.z += wgt * hb.z; accb.w += wgt * hb.w;
    }

    float inv = 1.f / (ssum + 1e-9f);
    float o[8] = {acca.x * inv, acca.y * inv, acca.z * inv, acca.w * inv,
                  accb.x * inv, accb.y * inv, accb.z * inv, accb.w * inv};
#pragma unroll
    for (int i = 0; i < 8; i++) o[i] = (o[i] > 0.f) ? o[i] : expm1f(o[i]);

    float* op = out + (size_t)v * HH + lane * 8;
    *(float4*)(op + 0) = make_float4(o[0], o[1], o[2], o[3]);
    *(float4*)(op + 4) = make_float4(o[4], o[5], o[6], o[7]);

    __nv_bfloat16 hi[8], lo[8];
#pragma unroll
    for (int i = 0; i < 8; i++) {
        hi[i] = __float2bfloat16(o[i]);
        lo[i] = __float2bfloat16(o[i] - __bfloat162float(hi[i]));
    }
    *(uint4*)(g_a_hi + (size_t)v * 256 + lane * 8) = *(const uint4*)hi;
    *(uint4*)(g_a_lo + (size_t)v * 256 + lane * 8) = *(const uint4*)lo;
}

// ---------------- final head ----------------
__global__ void __launch_bounds__(128) final_k(const float* __restrict__ feats,
                                               const float* __restrict__ Wout,
                                               const float* __restrict__ bout,
                                               float* __restrict__ out, int N) {
    int v = (blockIdx.x * 128 + threadIdx.x) >> 5;
    int lane = threadIdx.x & 31;
    if (v >= N) return;
    int idx = lane * 8;
    const float4* fp = (const float4*)(feats + (size_t)v * HH + idx);
    float4 fa = fp[0], fb = fp[1];
    const float4* wp = (const float4*)(Wout + (idx & 63));
    float4 wa = wp[0], wb = wp[1];
    float s = fa.x * wa.x + fa.y * wa.y + fa.z * wa.z + fa.w * wa.w +
              fb.x * wb.x + fb.y * wb.y + fb.z * wb.z + fb.w * wb.w;
#pragma unroll
    for (int off = 16; off >= 1; off >>= 1) s += __shfl_down_sync(0xffffffffu, s, off);
    if (lane == 0) {
        float r = 0.25f * s + bout[0];
        out[v] = (r > 0.f) ? r : 0.f;
    }
}

// ---------------- launch ----------------
extern "C" void kernel_launch(void* const* d_in, const int* in_sizes, int n_in,
                              void* d_out, int out_size) {
    const float* x    = (const float*)d_in[0];
    const int*   src  = (const int*)d_in[1];
    const int*   dst  = (const int*)d_in[2];
    const float* W0   = (const float*)d_in[3];
    const float* al0  = (const float*)d_in[4];
    const float* ar0  = (const float*)d_in[5];
    const float* W1   = (const float*)d_in[6];
    const float* al1  = (const float*)d_in[7];
    const float* ar1  = (const float*)d_in[8];
    const float* W2   = (const float*)d_in[9];
    const float* al2  = (const float*)d_in[10];
    const float* ar2  = (const float*)d_in[11];
    const float* Wout = (const float*)d_in[12];
    const float* bout = (const float*)d_in[13];

    const int N = N_NODES;
    const int E = N_EDGES;

    float *h, *h2;
    __nv_bfloat16 *ah, *al, *wh, *wl;
    cudaGetSymbolAddress((void**)&h, g_h);
    cudaGetSymbolAddress((void**)&h2, g_h2);
    cudaGetSymbolAddress((void**)&ah, g_a_hi);
    cudaGetSymbolAddress((void**)&al, g_a_lo);
    cudaGetSymbolAddress((void**)&wh, g_w_hi);
    cudaGetSymbolAddress((void**)&wl, g_w_lo);

    const int SMEM_SZ = 2 * STAGE_BYTES;   // 81920
    cudaFuncSetAttribute(gemm_mma_k<128>, cudaFuncAttributeMaxDynamicSharedMemorySize, SMEM_SZ);
    cudaFuncSetAttribute(gemm_mma_k<256>, cudaFuncAttributeMaxDynamicSharedMemorySize, SMEM_SZ);

    // CSR (dst-sorted)
    zero_counts_k<<<(N + 255) / 256, 256>>>();
    hist_k<<<(E + 255) / 256, 256>>>(dst, E);
    scan_k<<<1, 1024>>>();
    zero_counts_k<<<(N + 255) / 256, 256>>>();
    scatter_k<<<(E + 255) / 256, 256>>>(src, dst, E);

    // operand conversions
    convert_x_k<<<(N * 128 + 255) / 256, 256>>>(x, N * 128);
    convert_w_k<<<(128 * 256 + 255) / 256, 256>>>(W0, 128, wh + 0 * 65536, wl + 0 * 65536);
    convert_w_k<<<(256 * 256 + 255) / 256, 256>>>(W1, 256, wh + 1 * 65536, wl + 1 * 65536);
    convert_w_k<<<(256 * 256 + 255) / 256, 256>>>(W2, 256, wh + 2 * 65536, wl + 2 * 65536);

    dim3 ggrid(2, (N + 127) / 128);
    const int warpGrid = (N + 3) / 4;

    // layer 0 (K=128)
    gemm_mma_k<128><<<ggrid, 256, SMEM_SZ>>>(ah, al, wh + 0 * 65536, wl + 0 * 65536, h, al0, ar0);
    aggregate_k<<<warpGrid, 128>>>(h, h2, N);
    // layer 1 (K=256)
    gemm_mma_k<256><<<ggrid, 256, SMEM_SZ>>>(ah, al, wh + 1 * 65536, wl + 1 * 65536, h, al1, ar1);
    aggregate_k<<<warpGrid, 128>>>(h, h2, N);
    // layer 2 (K=256)
    gemm_mma_k<256><<<ggrid, 256, SMEM_SZ>>>(ah, al, wh + 2 * 65536, wl + 2 * 65536, h, al2, ar2);
    aggregate_k<<<warpGrid, 128>>>(h, h2, N);
    // output head
    final_k<<<warpGrid, 128>>>(h2, Wout, bout, (float*)d_out, N);
}

// round 5
// speedup vs baseline: 1.0230x; 1.0230x over previous
#include <cuda_runtime.h>
#include <cuda_bf16.h>
#include <cuda_fp16.h>
#include <math.h>
#include <stdint.h>

#define N_NODES 50000
#define N_EDGES 800000
#define HH 256
#define NHEADS 4
#define MPAD 50048

// ---------------- scratch ----------------
__device__ __half g_hf [(size_t)N_NODES * HH];   // GEMM output, fp16 (message payload)
__device__ float g_h2 [(size_t)N_NODES * HH];    // final-layer aggregate output (fp32)
__device__ float g_el [N_NODES * NHEADS];
__device__ float g_er [N_NODES * NHEADS];
__device__ int   g_rowptr[N_NODES + 1];
__device__ int   g_counts[N_NODES];
__device__ int   g_csr_src[N_EDGES];
__device__ __nv_bfloat16 g_a_hi[(size_t)MPAD * 256];
__device__ __nv_bfloat16 g_a_lo[(size_t)MPAD * 256];
__device__ __nv_bfloat16 g_w_hi[3 * 256 * 256];   // W^T per layer, [n][k]
__device__ __nv_bfloat16 g_w_lo[3 * 256 * 256];

// ---------------- CSR build ----------------
__global__ void zero_counts_k() {
    int i = blockIdx.x * blockDim.x + threadIdx.x;
    if (i < N_NODES) g_counts[i] = 0;
}
__global__ void hist_k(const int* __restrict__ dst, int E) {
    int i = blockIdx.x * blockDim.x + threadIdx.x;
    if (i < E) atomicAdd(&g_counts[dst[i]], 1);
}
__global__ void scan_k() {
    __shared__ int part[1024];
    const int C = (N_NODES + 1023) / 1024;
    int t = threadIdx.x;
    int base = t * C;
    int s = 0;
    for (int i = 0; i < C; i++) { int id = base + i; if (id < N_NODES) s += g_counts[id]; }
    part[t] = s;
    __syncthreads();
    for (int off = 1; off < 1024; off <<= 1) {
        int v = (t >= off) ? part[t - off] : 0;
        __syncthreads();
        part[t] += v;
        __syncthreads();
    }
    int run = (t == 0) ? 0 : part[t - 1];
    for (int i = 0; i < C; i++) {
        int id = base + i;
        if (id < N_NODES) { g_rowptr[id] = run; run += g_counts[id]; }
    }
    if (t == 1023) g_rowptr[N_NODES] = part[1023];
}
__global__ void scatter_k(const int* __restrict__ src, const int* __restrict__ dst, int E) {
    int i = blockIdx.x * blockDim.x + threadIdx.x;
    if (i < E) {
        int d = dst[i];
        int pos = g_rowptr[d] + atomicAdd(&g_counts[d], 1);
        g_csr_src[pos] = src[i];
    }
}

// ---------------- conversions ----------------
__global__ void convert_x_k(const float* __restrict__ x, int total) {
    int i = blockIdx.x * blockDim.x + threadIdx.x;
    if (i >= total) return;
    float a = x[i];
    __nv_bfloat16 hi = __float2bfloat16(a);
    __nv_bfloat16 lo = __float2bfloat16(a - __bfloat162float(hi));
    g_a_hi[i] = hi;
    g_a_lo[i] = lo;
}
__global__ void convert_w_k(const float* __restrict__ W, int K,
                            __nv_bfloat16* __restrict__ oh, __nv_bfloat16* __restrict__ ol) {
    int i = blockIdx.x * blockDim.x + threadIdx.x;
    if (i >= K * 256) return;
    int k = i / 256, n = i % 256;
    float a = W[i];
    __nv_bfloat16 hi = __float2bfloat16(a);
    __nv_bfloat16 lo = __float2bfloat16(a - __bfloat162float(hi));
    oh[(size_t)n * K + k] = hi;
    ol[(size_t)n * K + k] = lo;
}

// ---------------- warp-MMA helpers ----------------
__device__ __forceinline__ void ldsm4(uint32_t (&r)[4], uint32_t addr) {
    asm volatile("ldmatrix.sync.aligned.m8n8.x4.shared.b16 {%0,%1,%2,%3}, [%4];"
                 : "=r"(r[0]), "=r"(r[1]), "=r"(r[2]), "=r"(r[3]) : "r"(addr));
}
__device__ __forceinline__ void mma16816(float (&d)[4], const uint32_t (&a)[4],
                                         uint32_t b0, uint32_t b1) {
    asm volatile(
        "mma.sync.aligned.m16n8k16.row.col.f32.bf16.bf16.f32 "
        "{%0,%1,%2,%3}, {%4,%5,%6,%7}, {%8,%9}, {%0,%1,%2,%3};"
        : "+f"(d[0]), "+f"(d[1]), "+f"(d[2]), "+f"(d[3])
        : "r"(a[0]), "r"(a[1]), "r"(a[2]), "r"(a[3]), "r"(b0), "r"(b1));
}

// ---------------- tensor-core GEMM (static smem, single buffer) ----------------
// block tile 128x128, 8 warps (warp_m = wid&3 -> 32 rows, warp_n = wid>>2 -> 64 cols = one head)
#define LDA 80

template <int K>
__global__ void __launch_bounds__(256) gemm_mma_k(
    const __nv_bfloat16* __restrict__ Ah, const __nv_bfloat16* __restrict__ Al,
    const __nv_bfloat16* __restrict__ Bh, const __nv_bfloat16* __restrict__ Bl,
    __half* __restrict__ Cf, const float* __restrict__ alw, const float* __restrict__ arw)
{
    __shared__ __align__(16) uint8_t sAh[128 * LDA];
    __shared__ __align__(16) uint8_t sAl[128 * LDA];
    __shared__ __align__(16) uint8_t sBh[128 * LDA];
    __shared__ __align__(16) uint8_t sBl[128 * LDA];

    const int t = threadIdx.x;
    const int wid = t >> 5, lane = t & 31;
    const int warp_m = wid & 3, warp_n = wid >> 2;
    const int row0 = blockIdx.y * 128;
    const int nbase = blockIdx.x * 128;

    float acc[2][8][4];
#pragma unroll
    for (int i = 0; i < 2; i++)
#pragma unroll
        for (int j = 0; j < 8; j++)
#pragma unroll
            for (int q = 0; q < 4; q++) acc[i][j][q] = 0.f;

    const uint32_t uAh = (uint32_t)__cvta_generic_to_shared(sAh);
    const uint32_t uAl = (uint32_t)__cvta_generic_to_shared(sAl);
    const uint32_t uBh = (uint32_t)__cvta_generic_to_shared(sBh);
    const uint32_t uBl = (uint32_t)__cvta_generic_to_shared(sBl);
    const uint32_t rowOff = (uint32_t)(lane & 15) * LDA + (uint32_t)((lane >> 4) << 4);
    const uint32_t aOff = (uint32_t)warp_m * 32 * LDA + rowOff;
    const uint32_t bOff = (uint32_t)warp_n * 64 * LDA + rowOff;

    const int lrow = t >> 1;
    const int lkq = (t & 1) * 16;
    const uint4 zv = make_uint4(0, 0, 0, 0);
    const int arow = row0 + lrow;
    const bool aok = arow < N_NODES;
    const int brow = nbase + lrow;

    for (int k0 = 0; k0 < K; k0 += 32) {
        {
            const __nv_bfloat16* pa = Ah + (size_t)arow * K + k0 + lkq;
            const __nv_bfloat16* pl = Al + (size_t)arow * K + k0 + lkq;
            uint8_t* da = sAh + lrow * LDA + lkq * 2;
            uint8_t* dl = sAl + lrow * LDA + lkq * 2;
            *(uint4*)(da +  0) = aok ? ((const uint4*)pa)[0] : zv;
            *(uint4*)(da + 16) = aok ? ((const uint4*)pa)[1] : zv;
            *(uint4*)(dl +  0) = aok ? ((const uint4*)pl)[0] : zv;
            *(uint4*)(dl + 16) = aok ? ((const uint4*)pl)[1] : zv;
            const __nv_bfloat16* pb = Bh + (size_t)brow * K + k0 + lkq;
            const __nv_bfloat16* pq = Bl + (size_t)brow * K + k0 + lkq;
            uint8_t* db = sBh + lrow * LDA + lkq * 2;
            uint8_t* dq = sBl + lrow * LDA + lkq * 2;
            *(uint4*)(db +  0) = ((const uint4*)pb)[0];
            *(uint4*)(db + 16) = ((const uint4*)pb)[1];
            *(uint4*)(dq +  0) = ((const uint4*)pq)[0];
            *(uint4*)(dq + 16) = ((const uint4*)pq)[1];
        }
        __syncthreads();

#pragma unroll
        for (int kk = 0; kk < 2; kk++) {
            const uint32_t kb = kk * 32;
            uint32_t aH[2][4], aL[2][4], bH[4][4], bL[4][4];
#pragma unroll
            for (int mt = 0; mt < 2; mt++) ldsm4(aH[mt], uAh + aOff + mt * 16 * LDA + kb);
#pragma unroll
            for (int p = 0; p < 4; p++) ldsm4(bH[p], uBh + bOff + p * 16 * LDA + kb);
#pragma unroll
            for (int mt = 0; mt < 2; mt++)
#pragma unroll
                for (int p = 0; p < 4; p++) {
                    mma16816(acc[mt][2 * p + 0], aH[mt], bH[p][0], bH[p][2]);
                    mma16816(acc[mt][2 * p + 1], aH[mt], bH[p][1], bH[p][3]);
                }
#pragma unroll
            for (int p = 0; p < 4; p++) ldsm4(bL[p], uBl + bOff + p * 16 * LDA + kb);
#pragma unroll
            for (int mt = 0; mt < 2; mt++)
#pragma unroll
                for (int p = 0; p < 4; p++) {
                    mma16816(acc[mt][2 * p + 0], aH[mt], bL[p][0], bL[p][2]);
                    mma16816(acc[mt][2 * p + 1], aH[mt], bL[p][1], bL[p][3]);
                }
#pragma unroll
            for (int mt = 0; mt < 2; mt++) ldsm4(aL[mt], uAl + aOff + mt * 16 * LDA + kb);
#pragma unroll
            for (int mt = 0; mt < 2; mt++)
#pragma unroll
                for (int p = 0; p < 4; p++) {
                    mma16816(acc[mt][2 * p + 0], aL[mt], bH[p][0], bH[p][2]);
                    mma16816(acc[mt][2 * p + 1], aL[mt], bH[p][1], bH[p][3]);
                }
        }
        __syncthreads();
    }

    // ---- epilogue: fp16 h + fused attention scores (unique writer per row/head) ----
    const int g = lane >> 2;
    const int tig = lane & 3;
    const int head = blockIdx.x * 2 + warp_n;
    const int cihb = tig * 2;

#pragma unroll
    for (int mt = 0; mt < 2; mt++) {
#pragma unroll
        for (int half = 0; half < 2; half++) {
            int grow = row0 + warp_m * 32 + mt * 16 + g + half * 8;
            if (grow >= N_NODES) continue;
            float sl = 0.f, sr = 0.f;
            __half* cp = Cf + (size_t)grow * 256 + nbase + warp_n * 64;
#pragma unroll
            for (int nt = 0; nt < 8; nt++) {
                float c0 = acc[mt][nt][half * 2 + 0];
                float c1 = acc[mt][nt][half * 2 + 1];
                int cih = nt * 8 + cihb;
                *(__half2*)(cp + cih) = __floats2half2_rn(c0, c1);
                sl += c0 * alw[head * 64 + cih] + c1 * alw[head * 64 + cih + 1];
                sr += c0 * arw[head * 64 + cih] + c1 * arw[head * 64 + cih + 1];
            }
            sl += __shfl_xor_sync(0xffffffffu, sl, 1);
            sl += __shfl_xor_sync(0xffffffffu, sl, 2);
            sr += __shfl_xor_sync(0xffffffffu, sr, 1);
            sr += __shfl_xor_sync(0xffffffffu, sr, 2);
            if (tig == 0) {
                g_el[grow * 4 + head] = sl;
                g_er[grow * 4 + head] = sr;
            }
        }
    }
}

// ---------------- fused edge softmax + aggregate + ELU ----------------
// LAST=false: emit bf16 hi/lo for next GEMM; LAST=true: emit fp32 feats for final head
template <bool LAST>
__global__ void __launch_bounds__(128) aggregate_k(const __half* __restrict__ hf,
                                                   float* __restrict__ out32, int N) {
    int v = (blockIdx.x * 128 + threadIdx.x) >> 5;
    int lane = threadIdx.x & 31;
    if (v >= N) return;
    int hd = lane >> 3;

    float4 er4 = ((const float4*)g_er)[v];
    float erv = (hd == 0) ? er4.x : (hd == 1) ? er4.y : (hd == 2) ? er4.z : er4.w;

    int r0 = g_rowptr[v];
    int r1 = g_rowptr[v + 1];

    // ---- pass 1: max (prefetch pipeline) ----
    float m = -INFINITY;
    if (r0 < r1) {
        int s = g_csr_src[r0];
        for (int j = r0; j < r1; j++) {
            int s_cur = s;
            if (j + 1 < r1) s = g_csr_src[j + 1];
            float4 el4 = ((const float4*)g_el)[s_cur];
            float elv = (hd == 0) ? el4.x : (hd == 1) ? el4.y : (hd == 2) ? el4.z : el4.w;
            float e = elv + erv;
            e = (e > 0.f) ? e : 0.2f * e;
            m = fmaxf(m, e);
        }
    }

    // ---- pass 2: weighted accumulate (prefetch pipeline) ----
    float ssum = 0.f;
    float4 acca = make_float4(0.f, 0.f, 0.f, 0.f);
    float4 accb = make_float4(0.f, 0.f, 0.f, 0.f);
    if (r0 < r1) {
        int s = g_csr_src[r0];
        float4 el4 = ((const float4*)g_el)[s];
        uint4 hv = *(const uint4*)(hf + (size_t)s * HH + lane * 8);
        for (int j = r0; j < r1; j++) {
            float4 el4c = el4;
            uint4 hvc = hv;
            if (j + 1 < r1) {
                int sn = g_csr_src[j + 1];
                el4 = ((const float4*)g_el)[sn];
                hv = *(const uint4*)(hf + (size_t)sn * HH + lane * 8);
            }
            float elv = (hd == 0) ? el4c.x : (hd == 1) ? el4c.y : (hd == 2) ? el4c.z : el4c.w;
            float e = elv + erv;
            e = (e > 0.f) ? e : 0.2f * e;
            float wgt = __expf(e - m);
            ssum += wgt;
            const __half2* hp = (const __half2*)&hvc;
            float2 f0 = __half22float2(hp[0]);
            float2 f1 = __half22float2(hp[1]);
            float2 f2 = __half22float2(hp[2]);
            float2 f3 = __half22float2(hp[3]);
            acca.x += wgt * f0.x; acca.y += wgt * f0.y;
            acca.z += wgt * f1.x; acca.w += wgt * f1.y;
            accb.x += wgt * f2.x; accb.y += wgt * f2.y;
            accb.z += wgt * f3.x; accb.w += wgt * f3.y;
        }
    }

    float inv = 1.f / (ssum + 1e-9f);
    float o[8] = {acca.x * inv, acca.y * inv, acca.z * inv, acca.w * inv,
                  accb.x * inv, accb.y * inv, accb.z * inv, accb.w * inv};
#pragma unroll
    for (int i = 0; i < 8; i++) o[i] = (o[i] > 0.f) ? o[i] : expm1f(o[i]);

    if (LAST) {
        float* op = out32 + (size_t)v * HH + lane * 8;
        *(float4*)(op + 0) = make_float4(o[0], o[1], o[2], o[3]);
        *(float4*)(op + 4) = make_float4(o[4], o[5], o[6], o[7]);
    } else {
        __nv_bfloat16 hi[8], lo[8];
#pragma unroll
        for (int i = 0; i < 8; i++) {
            hi[i] = __float2bfloat16(o[i]);
            lo[i] = __float2bfloat16(o[i] - __bfloat162float(hi[i]));
        }
        *(uint4*)(g_a_hi + (size_t)v * 256 + lane * 8) = *(const uint4*)hi;
        *(uint4*)(g_a_lo + (size_t)v * 256 + lane * 8) = *(const uint4*)lo;
    }
}

// ---------------- final head ----------------
__global__ void __launch_bounds__(128) final_k(const float* __restrict__ feats,
                                               const float* __restrict__ Wout,
                                               const float* __restrict__ bout,
                                               float* __restrict__ out, int N) {
    int v = (blockIdx.x * 128 + threadIdx.x) >> 5;
    int lane = threadIdx.x & 31;
    if (v >= N) return;
    int idx = lane * 8;
    const float4* fp = (const float4*)(feats + (size_t)v * HH + idx);
    float4 fa = fp[0], fb = fp[1];
    const float4* wp = (const float4*)(Wout + (idx & 63));
    float4 wa = wp[0], wb = wp[1];
    float s = fa.x * wa.x + fa.y * wa.y + fa.z * wa.z + fa.w * wa.w +
              fb.x * wb.x + fb.y * wb.y + fb.z * wb.z + fb.w * wb.w;
#pragma unroll
    for (int off = 16; off >= 1; off >>= 1) s += __shfl_down_sync(0xffffffffu, s, off);
    if (lane == 0) {
        float r = 0.25f * s + bout[0];
        out[v] = (r > 0.f) ? r : 0.f;
    }
}

// ---------------- launch ----------------
extern "C" void kernel_launch(void* const* d_in, const int* in_sizes, int n_in,
                              void* d_out, int out_size) {
    const float* x    = (const float*)d_in[0];
    const int*   src  = (const int*)d_in[1];
    const int*   dst  = (const int*)d_in[2];
    const float* W0   = (const float*)d_in[3];
    const float* al0  = (const float*)d_in[4];
    const float* ar0  = (const float*)d_in[5];
    const float* W1   = (const float*)d_in[6];
    const float* al1  = (const float*)d_in[7];
    const float* ar1  = (const float*)d_in[8];
    const float* W2   = (const float*)d_in[9];
    const float* al2  = (const float*)d_in[10];
    const float* ar2  = (const float*)d_in[11];
    const float* Wout = (const float*)d_in[12];
    const float* bout = (const float*)d_in[13];

    const int N = N_NODES;
    const int E = N_EDGES;

    float *h2;
    __half *hf;
    __nv_bfloat16 *ah, *al, *wh, *wl;
    cudaGetSymbolAddress((void**)&hf, g_hf);
    cudaGetSymbolAddress((void**)&h2, g_h2);
    cudaGetSymbolAddress((void**)&ah, g_a_hi);
    cudaGetSymbolAddress((void**)&al, g_a_lo);
    cudaGetSymbolAddress((void**)&wh, g_w_hi);
    cudaGetSymbolAddress((void**)&wl, g_w_lo);

    // CSR (dst-sorted)
    zero_counts_k<<<(N + 255) / 256, 256>>>();
    hist_k<<<(E + 255) / 256, 256>>>(dst, E);
    scan_k<<<1, 1024>>>();
    zero_counts_k<<<(N + 255) / 256, 256>>>();
    scatter_k<<<(E + 255) / 256, 256>>>(src, dst, E);

    // operand conversions
    convert_x_k<<<(N * 128 + 255) / 256, 256>>>(x, N * 128);
    convert_w_k<<<(128 * 256 + 255) / 256, 256>>>(W0, 128, wh + 0 * 65536, wl + 0 * 65536);
    convert_w_k<<<(256 * 256 + 255) / 256, 256>>>(W1, 256, wh + 1 * 65536, wl + 1 * 65536);
    convert_w_k<<<(256 * 256 + 255) / 256, 256>>>(W2, 256, wh + 2 * 65536, wl + 2 * 65536);

    dim3 ggrid(2, (N + 127) / 128);
    const int warpGrid = (N + 3) / 4;

    // layer 0 (K=128)
    gemm_mma_k<128><<<ggrid, 256>>>(ah, al, wh + 0 * 65536, wl + 0 * 65536, hf, al0, ar0);
    aggregate_k<false><<<warpGrid, 128>>>(hf, nullptr, N);
    // layer 1 (K=256)
    gemm_mma_k<256><<<ggrid, 256>>>(ah, al, wh + 1 * 65536, wl + 1 * 65536, hf, al1, ar1);
    aggregate_k<false><<<warpGrid, 128>>>(hf, nullptr, N);
    // layer 2 (K=256)
    gemm_mma_k<256><<<ggrid, 256>>>(ah, al, wh + 2 * 65536, wl + 2 * 65536, hf, al2, ar2);
    aggregate_k<true><<<warpGrid, 128>>>(hf, h2, N);
    // output head
    final_k<<<warpGrid, 128>>>(h2, Wout, bout, (float*)d_out, N);
}

// round 6
// speedup vs baseline: 1.0881x; 1.0637x over previous
#include <cuda_runtime.h>
#include <cuda_bf16.h>
#include <math.h>
#include <stdint.h>

#define N_NODES 50000
#define N_EDGES 800000
#define HH 256
#define NHEADS 4
#define MPAD 50048

// ---------------- scratch ----------------
__device__ float g_h  [(size_t)N_NODES * HH];   // GEMM output (fp32 message payload)
__device__ float g_el [N_NODES * NHEADS];
__device__ float g_er [N_NODES * NHEADS];
__device__ int   g_rowptr[N_NODES + 1];
__device__ int   g_counts[N_NODES];
__device__ int   g_csr_src[N_EDGES];
__device__ __nv_bfloat16 g_a_hi[(size_t)MPAD * 256];
__device__ __nv_bfloat16 g_a_lo[(size_t)MPAD * 256];
__device__ __nv_bfloat16 g_w_hi[3 * 256 * 256];   // W^T per layer, [n][k]
__device__ __nv_bfloat16 g_w_lo[3 * 256 * 256];

// ---------------- CSR build ----------------
__global__ void zero_counts_k() {
    int i = blockIdx.x * blockDim.x + threadIdx.x;
    if (i < N_NODES) g_counts[i] = 0;
}
__global__ void hist_k(const int* __restrict__ dst, int E) {
    int i = blockIdx.x * blockDim.x + threadIdx.x;
    if (i < E) atomicAdd(&g_counts[dst[i]], 1);
}
__global__ void scan_k() {
    __shared__ int part[1024];
    const int C = (N_NODES + 1023) / 1024;
    int t = threadIdx.x;
    int base = t * C;
    int s = 0;
    for (int i = 0; i < C; i++) { int id = base + i; if (id < N_NODES) s += g_counts[id]; }
    part[t] = s;
    __syncthreads();
    for (int off = 1; off < 1024; off <<= 1) {
        int v = (t >= off) ? part[t - off] : 0;
        __syncthreads();
        part[t] += v;
        __syncthreads();
    }
    int run = (t == 0) ? 0 : part[t - 1];
    for (int i = 0; i < C; i++) {
        int id = base + i;
        if (id < N_NODES) { g_rowptr[id] = run; run += g_counts[id]; }
    }
    if (t == 1023) g_rowptr[N_NODES] = part[1023];
}
__global__ void scatter_k(const int* __restrict__ src, const int* __restrict__ dst, int E) {
    int i = blockIdx.x * blockDim.x + threadIdx.x;
    if (i < E) {
        int d = dst[i];
        int pos = g_rowptr[d] + atomicAdd(&g_counts[d], 1);
        g_csr_src[pos] = src[i];
    }
}

// ---------------- conversions ----------------
__global__ void convert_x_k(const float* __restrict__ x, int total) {
    int i = blockIdx.x * blockDim.x + threadIdx.x;
    if (i >= total) return;
    float a = x[i];
    __nv_bfloat16 hi = __float2bfloat16(a);
    __nv_bfloat16 lo = __float2bfloat16(a - __bfloat162float(hi));
    g_a_hi[i] = hi;
    g_a_lo[i] = lo;
}
__global__ void convert_w_k(const float* __restrict__ W, int K,
                            __nv_bfloat16* __restrict__ oh, __nv_bfloat16* __restrict__ ol) {
    int i = blockIdx.x * blockDim.x + threadIdx.x;
    if (i >= K * 256) return;
    int k = i / 256, n = i % 256;
    float a = W[i];
    __nv_bfloat16 hi = __float2bfloat16(a);
    __nv_bfloat16 lo = __float2bfloat16(a - __bfloat162float(hi));
    oh[(size_t)n * K + k] = hi;
    ol[(size_t)n * K + k] = lo;
}

// ---------------- warp-MMA helpers ----------------
__device__ __forceinline__ void ldsm4(uint32_t (&r)[4], uint32_t addr) {
    asm volatile("ldmatrix.sync.aligned.m8n8.x4.shared.b16 {%0,%1,%2,%3}, [%4];"
                 : "=r"(r[0]), "=r"(r[1]), "=r"(r[2]), "=r"(r[3]) : "r"(addr));
}
__device__ __forceinline__ void mma16816(float (&d)[4], const uint32_t (&a)[4],
                                         uint32_t b0, uint32_t b1) {
    asm volatile(
        "mma.sync.aligned.m16n8k16.row.col.f32.bf16.bf16.f32 "
        "{%0,%1,%2,%3}, {%4,%5,%6,%7}, {%8,%9}, {%0,%1,%2,%3};"
        : "+f"(d[0]), "+f"(d[1]), "+f"(d[2]), "+f"(d[3])
        : "r"(a[0]), "r"(a[1]), "r"(a[2]), "r"(a[3]), "r"(b0), "r"(b1));
}

// ---------------- tensor-core GEMM (static smem, 2 blocks/SM forced) ----------------
// block tile 128x128, 8 warps (warp_m = wid&3 -> 32 rows, warp_n = wid>>2 -> 64 cols = one head)
#define LDA 80

template <int K>
__global__ void __launch_bounds__(256, 2) gemm_mma_k(
    const __nv_bfloat16* __restrict__ Ah, const __nv_bfloat16* __restrict__ Al,
    const __nv_bfloat16* __restrict__ Bh, const __nv_bfloat16* __restrict__ Bl,
    float* __restrict__ C, const float* __restrict__ alw, const float* __restrict__ arw)
{
    __shared__ __align__(16) uint8_t sAh[128 * LDA];
    __shared__ __align__(16) uint8_t sAl[128 * LDA];
    __shared__ __align__(16) uint8_t sBh[128 * LDA];
    __shared__ __align__(16) uint8_t sBl[128 * LDA];

    const int t = threadIdx.x;
    const int wid = t >> 5, lane = t & 31;
    const int warp_m = wid & 3, warp_n = wid >> 2;
    const int row0 = blockIdx.y * 128;
    const int nbase = blockIdx.x * 128;

    float acc[2][8][4];
#pragma unroll
    for (int i = 0; i < 2; i++)
#pragma unroll
        for (int j = 0; j < 8; j++)
#pragma unroll
            for (int q = 0; q < 4; q++) acc[i][j][q] = 0.f;

    const uint32_t uAh = (uint32_t)__cvta_generic_to_shared(sAh);
    const uint32_t uAl = (uint32_t)__cvta_generic_to_shared(sAl);
    const uint32_t uBh = (uint32_t)__cvta_generic_to_shared(sBh);
    const uint32_t uBl = (uint32_t)__cvta_generic_to_shared(sBl);
    const uint32_t rowOff = (uint32_t)(lane & 15) * LDA + (uint32_t)((lane >> 4) << 4);
    const uint32_t aOff = (uint32_t)warp_m * 32 * LDA + rowOff;
    const uint32_t bOff = (uint32_t)warp_n * 64 * LDA + rowOff;

    const int lrow = t >> 1;
    const int lkq = (t & 1) * 16;
    const uint4 zv = make_uint4(0, 0, 0, 0);
    const int arow = row0 + lrow;
    const bool aok = arow < N_NODES;
    const int brow = nbase + lrow;

    for (int k0 = 0; k0 < K; k0 += 32) {
        {
            const __nv_bfloat16* pa = Ah + (size_t)arow * K + k0 + lkq;
            const __nv_bfloat16* pl = Al + (size_t)arow * K + k0 + lkq;
            uint8_t* da = sAh + lrow * LDA + lkq * 2;
            uint8_t* dl = sAl + lrow * LDA + lkq * 2;
            *(uint4*)(da +  0) = aok ? ((const uint4*)pa)[0] : zv;
            *(uint4*)(da + 16) = aok ? ((const uint4*)pa)[1] : zv;
            *(uint4*)(dl +  0) = aok ? ((const uint4*)pl)[0] : zv;
            *(uint4*)(dl + 16) = aok ? ((const uint4*)pl)[1] : zv;
            const __nv_bfloat16* pb = Bh + (size_t)brow * K + k0 + lkq;
            const __nv_bfloat16* pq = Bl + (size_t)brow * K + k0 + lkq;
            uint8_t* db = sBh + lrow * LDA + lkq * 2;
            uint8_t* dq = sBl + lrow * LDA + lkq * 2;
            *(uint4*)(db +  0) = ((const uint4*)pb)[0];
            *(uint4*)(db + 16) = ((const uint4*)pb)[1];
            *(uint4*)(dq +  0) = ((const uint4*)pq)[0];
            *(uint4*)(dq + 16) = ((const uint4*)pq)[1];
        }
        __syncthreads();

#pragma unroll
        for (int kk = 0; kk < 2; kk++) {
            const uint32_t kb = kk * 32;
            // ordered so bH dies before bL loads (register pressure < 128)
            uint32_t aH[2][4];
#pragma unroll
            for (int mt = 0; mt < 2; mt++) ldsm4(aH[mt], uAh + aOff + mt * 16 * LDA + kb);
            {
                uint32_t bH[4][4];
#pragma unroll
                for (int p = 0; p < 4; p++) ldsm4(bH[p], uBh + bOff + p * 16 * LDA + kb);
#pragma unroll
                for (int mt = 0; mt < 2; mt++)
#pragma unroll
                    for (int p = 0; p < 4; p++) {
                        mma16816(acc[mt][2 * p + 0], aH[mt], bH[p][0], bH[p][2]);
                        mma16816(acc[mt][2 * p + 1], aH[mt], bH[p][1], bH[p][3]);
                    }
                uint32_t aL[2][4];
#pragma unroll
                for (int mt = 0; mt < 2; mt++) ldsm4(aL[mt], uAl + aOff + mt * 16 * LDA + kb);
#pragma unroll
                for (int mt = 0; mt < 2; mt++)
#pragma unroll
                    for (int p = 0; p < 4; p++) {
                        mma16816(acc[mt][2 * p + 0], aL[mt], bH[p][0], bH[p][2]);
                        mma16816(acc[mt][2 * p + 1], aL[mt], bH[p][1], bH[p][3]);
                    }
            }
            {
                uint32_t bL[4][4];
#pragma unroll
                for (int p = 0; p < 4; p++) ldsm4(bL[p], uBl + bOff + p * 16 * LDA + kb);
#pragma unroll
                for (int mt = 0; mt < 2; mt++)
#pragma unroll
                    for (int p = 0; p < 4; p++) {
                        mma16816(acc[mt][2 * p + 0], aH[mt], bL[p][0], bL[p][2]);
                        mma16816(acc[mt][2 * p + 1], aH[mt], bL[p][1], bL[p][3]);
                    }
            }
        }
        __syncthreads();
    }

    // ---- epilogue: fp32 h + fused attention scores (unique writer per row/head) ----
    const int g = lane >> 2;
    const int tig = lane & 3;
    const int head = blockIdx.x * 2 + warp_n;
    const int cihb = tig * 2;

#pragma unroll
    for (int mt = 0; mt < 2; mt++) {
#pragma unroll
        for (int half = 0; half < 2; half++) {
            int grow = row0 + warp_m * 32 + mt * 16 + g + half * 8;
            if (grow >= N_NODES) continue;
            float sl = 0.f, sr = 0.f;
            float* cp = C + (size_t)grow * 256 + nbase + warp_n * 64;
#pragma unroll
            for (int nt = 0; nt < 8; nt++) {
                float c0 = acc[mt][nt][half * 2 + 0];
                float c1 = acc[mt][nt][half * 2 + 1];
                int cih = nt * 8 + cihb;
                *(float2*)(cp + cih) = make_float2(c0, c1);
                sl += c0 * alw[head * 64 + cih] + c1 * alw[head * 64 + cih + 1];
                sr += c0 * arw[head * 64 + cih] + c1 * arw[head * 64 + cih + 1];
            }
            sl += __shfl_xor_sync(0xffffffffu, sl, 1);
            sl += __shfl_xor_sync(0xffffffffu, sl, 2);
            sr += __shfl_xor_sync(0xffffffffu, sr, 1);
            sr += __shfl_xor_sync(0xffffffffu, sr, 2);
            if (tig == 0) {
                g_el[grow * 4 + head] = sl;
                g_er[grow * 4 + head] = sr;
            }
        }
    }
}

// ---------------- single-pass online-softmax aggregate + ELU ----------------
// LAST=false: emit bf16 hi/lo for next GEMM
// LAST=true:  fused final head -> out[v] = relu(mean_heads(o) @ Wout + bout)
template <bool LAST>
__global__ void __launch_bounds__(128) aggregate_k(const float* __restrict__ h,
                                                   float* __restrict__ out,
                                                   const float* __restrict__ Wout,
                                                   const float* __restrict__ bout, int N) {
    int v = (blockIdx.x * 128 + threadIdx.x) >> 5;
    int lane = threadIdx.x & 31;
    if (v >= N) return;
    int hd = lane >> 3;

    float4 er4 = ((const float4*)g_er)[v];
    float erv = (hd == 0) ? er4.x : (hd == 1) ? er4.y : (hd == 2) ? er4.z : er4.w;

    int r0 = g_rowptr[v];
    int r1 = g_rowptr[v + 1];

    float m = -INFINITY, ssum = 0.f;
    float4 acca = make_float4(0.f, 0.f, 0.f, 0.f);
    float4 accb = make_float4(0.f, 0.f, 0.f, 0.f);

    if (r0 < r1) {
        // software-pipelined single pass (prefetch depth 1)
        int s = g_csr_src[r0];
        float4 el4 = ((const float4*)g_el)[s];
        const float4* hp = (const float4*)(h + (size_t)s * HH + lane * 8);
        float4 ha = hp[0], hb = hp[1];
        for (int j = r0; j < r1; j++) {
            float4 el4c = el4;
            float4 hac = ha, hbc = hb;
            if (j + 1 < r1) {
                int sn = g_csr_src[j + 1];
                el4 = ((const float4*)g_el)[sn];
                const float4* hq = (const float4*)(h + (size_t)sn * HH + lane * 8);
                ha = hq[0]; hb = hq[1];
            }
            float elv = (hd == 0) ? el4c.x : (hd == 1) ? el4c.y : (hd == 2) ? el4c.z : el4c.w;
            float e = elv + erv;
            e = (e > 0.f) ? e : 0.2f * e;
            float mn = fmaxf(m, e);
            float sc = __expf(m - mn);     // first iter: exp(-inf)=0
            float w  = __expf(e - mn);
            m = mn;
            ssum = ssum * sc + w;
            acca.x = acca.x * sc + w * hac.x; acca.y = acca.y * sc + w * hac.y;
            acca.z = acca.z * sc + w * hac.z; acca.w = acca.w * sc + w * hac.w;
            accb.x = accb.x * sc + w * hbc.x; accb.y = accb.y * sc + w * hbc.y;
            accb.z = accb.z * sc + w * hbc.z; accb.w = accb.w * sc + w * hbc.w;
        }
    }

    float inv = 1.f / (ssum + 1e-9f);
    float o[8] = {acca.x * inv, acca.y * inv, acca.z * inv, acca.w * inv,
                  accb.x * inv, accb.y * inv, accb.z * inv, accb.w * inv};
#pragma unroll
    for (int i = 0; i < 8; i++) o[i] = (o[i] > 0.f) ? o[i] : expm1f(o[i]);

    if (LAST) {
        // fused head: s = sum_{heads,dims} o * Wout[dim]; out = relu(0.25*s + bout)
        const int dbase = (lane & 7) * 8;
        float s = 0.f;
#pragma unroll
        for (int i = 0; i < 8; i++) s += o[i] * Wout[dbase + i];
#pragma unroll
        for (int off = 16; off >= 1; off >>= 1) s += __shfl_xor_sync(0xffffffffu, s, off);
        if (lane == 0) {
            float r = 0.25f * s + bout[0];
            out[v] = (r > 0.f) ? r : 0.f;
        }
    } else {
        __nv_bfloat16 hi[8], lo[8];
#pragma unroll
        for (int i = 0; i < 8; i++) {
            hi[i] = __float2bfloat16(o[i]);
            lo[i] = __float2bfloat16(o[i] - __bfloat162float(hi[i]));
        }
        *(uint4*)(g_a_hi + (size_t)v * 256 + lane * 8) = *(const uint4*)hi;
        *(uint4*)(g_a_lo + (size_t)v * 256 + lane * 8) = *(const uint4*)lo;
    }
}

// ---------------- launch ----------------
extern "C" void kernel_launch(void* const* d_in, const int* in_sizes, int n_in,
                              void* d_out, int out_size) {
    const float* x    = (const float*)d_in[0];
    const int*   src  = (const int*)d_in[1];
    const int*   dst  = (const int*)d_in[2];
    const float* W0   = (const float*)d_in[3];
    const float* al0  = (const float*)d_in[4];
    const float* ar0  = (const float*)d_in[5];
    const float* W1   = (const float*)d_in[6];
    const float* al1  = (const float*)d_in[7];
    const float* ar1  = (const float*)d_in[8];
    const float* W2   = (const float*)d_in[9];
    const float* al2  = (const float*)d_in[10];
    const float* ar2  = (const float*)d_in[11];
    const float* Wout = (const float*)d_in[12];
    const float* bout = (const float*)d_in[13];

    const int N = N_NODES;
    const int E = N_EDGES;

    float *h;
    __nv_bfloat16 *ah, *al, *wh, *wl;
    cudaGetSymbolAddress((void**)&h, g_h);
    cudaGetSymbolAddress((void**)&ah, g_a_hi);
    cudaGetSymbolAddress((void**)&al, g_a_lo);
    cudaGetSymbolAddress((void**)&wh, g_w_hi);
    cudaGetSymbolAddress((void**)&wl, g_w_lo);

    // CSR (dst-sorted)
    zero_counts_k<<<(N + 255) / 256, 256>>>();
    hist_k<<<(E + 255) / 256, 256>>>(dst, E);
    scan_k<<<1, 1024>>>();
    zero_counts_k<<<(N + 255) / 256, 256>>>();
    scatter_k<<<(E + 255) / 256, 256>>>(src, dst, E);

    // operand conversions
    convert_x_k<<<(N * 128 + 255) / 256, 256>>>(x, N * 128);
    convert_w_k<<<(128 * 256 + 255) / 256, 256>>>(W0, 128, wh + 0 * 65536, wl + 0 * 65536);
    convert_w_k<<<(256 * 256 + 255) / 256, 256>>>(W1, 256, wh + 1 * 65536, wl + 1 * 65536);
    convert_w_k<<<(256 * 256 + 255) / 256, 256>>>(W2, 256, wh + 2 * 65536, wl + 2 * 65536);

    dim3 ggrid(2, (N + 127) / 128);
    const int warpGrid = (N + 3) / 4;

    // layer 0 (K=128)
    gemm_mma_k<128><<<ggrid, 256>>>(ah, al, wh + 0 * 65536, wl + 0 * 65536, h, al0, ar0);
    aggregate_k<false><<<warpGrid, 128>>>(h, nullptr, nullptr, nullptr, N);
    // layer 1 (K=256)
    gemm_mma_k<256><<<ggrid, 256>>>(ah, al, wh + 1 * 65536, wl + 1 * 65536, h, al1, ar1);
    aggregate_k<false><<<warpGrid, 128>>>(h, nullptr, nullptr, nullptr, N);
    // layer 2 (K=256) + fused final head
    gemm_mma_k<256><<<ggrid, 256>>>(ah, al, wh + 2 * 65536, wl + 2 * 65536, h, al2, ar2);
    aggregate_k<true><<<warpGrid, 128>>>(h, (float*)d_out, Wout, bout, N);
}

// round 7
// speedup vs baseline: 1.1110x; 1.0210x over previous
#include <cuda_runtime.h>
#include <cuda_bf16.h>
#include <math.h>
#include <stdint.h>

#define N_NODES 50000
#define N_EDGES 800000
#define HH 256
#define NHEADS 4
#define MPAD 50048

// ---------------- scratch ----------------
__device__ float g_h  [(size_t)N_NODES * HH];   // GEMM output (fp32 message payload)
__device__ float g_el [N_NODES * NHEADS];
__device__ float g_er [N_NODES * NHEADS];
__device__ int   g_rowptr[N_NODES + 1];
__device__ int   g_counts[N_NODES];
__device__ int   g_csr_src[N_EDGES];
__device__ __nv_bfloat16 g_a_hi[(size_t)MPAD * 256];
__device__ __nv_bfloat16 g_a_lo[(size_t)MPAD * 256];
__device__ __nv_bfloat16 g_w_hi[3 * 256 * 256];   // W^T per layer, [n][k]
__device__ __nv_bfloat16 g_w_lo[3 * 256 * 256];

// ---------------- conversions (+ fused count zeroing) ----------------
__global__ void convert_x_k(const float* __restrict__ x, int total) {
    int i = blockIdx.x * blockDim.x + threadIdx.x;
    if (i < N_NODES) g_counts[i] = 0;   // fused: zero histogram counters
    if (i >= total) return;
    float a = x[i];
    __nv_bfloat16 hi = __float2bfloat16(a);
    __nv_bfloat16 lo = __float2bfloat16(a - __bfloat162float(hi));
    g_a_hi[i] = hi;
    g_a_lo[i] = lo;
}

// all 3 weight matrices in one launch
__global__ void convert_w_all_k(const float* __restrict__ W0,
                                const float* __restrict__ W1,
                                const float* __restrict__ W2) {
    int i = blockIdx.x * blockDim.x + threadIdx.x;
    const float* W;
    __nv_bfloat16 *oh, *ol;
    int K, idx;
    if (i < 128 * 256) {                 // layer 0, K=128
        W = W0; K = 128; idx = i;
        oh = g_w_hi + 0 * 65536; ol = g_w_lo + 0 * 65536;
    } else if (i < 128 * 256 + 256 * 256) {
        W = W1; K = 256; idx = i - 128 * 256;
        oh = g_w_hi + 1 * 65536; ol = g_w_lo + 1 * 65536;
    } else if (i < 128 * 256 + 2 * 256 * 256) {
        W = W2; K = 256; idx = i - 128 * 256 - 256 * 256;
        oh = g_w_hi + 2 * 65536; ol = g_w_lo + 2 * 65536;
    } else return;
    int k = idx / 256, n = idx % 256;
    float a = W[idx];
    __nv_bfloat16 hi = __float2bfloat16(a);
    __nv_bfloat16 lo = __float2bfloat16(a - __bfloat162float(hi));
    oh[(size_t)n * K + k] = hi;
    ol[(size_t)n * K + k] = lo;
}

// ---------------- CSR build ----------------
__global__ void hist_k(const int* __restrict__ dst, int E) {
    int i = blockIdx.x * blockDim.x + threadIdx.x;
    if (i < E) atomicAdd(&g_counts[dst[i]], 1);
}
// scan + re-zero counts (cursors for scatter)
__global__ void scan_k() {
    __shared__ int part[1024];
    const int C = (N_NODES + 1023) / 1024;
    int t = threadIdx.x;
    int base = t * C;
    int s = 0;
    for (int i = 0; i < C; i++) { int id = base + i; if (id < N_NODES) s += g_counts[id]; }
    part[t] = s;
    __syncthreads();
    for (int off = 1; off < 1024; off <<= 1) {
        int v = (t >= off) ? part[t - off] : 0;
        __syncthreads();
        part[t] += v;
        __syncthreads();
    }
    int run = (t == 0) ? 0 : part[t - 1];
    for (int i = 0; i < C; i++) {
        int id = base + i;
        if (id < N_NODES) {
            g_rowptr[id] = run;
            run += g_counts[id];
            g_counts[id] = 0;            // fused: reset cursor
        }
    }
    if (t == 1023) g_rowptr[N_NODES] = part[1023];
}
__global__ void scatter_k(const int* __restrict__ src, const int* __restrict__ dst, int E) {
    int i = blockIdx.x * blockDim.x + threadIdx.x;
    if (i < E) {
        int d = dst[i];
        int pos = g_rowptr[d] + atomicAdd(&g_counts[d], 1);
        g_csr_src[pos] = src[i];
    }
}

// ---------------- warp-MMA helpers ----------------
__device__ __forceinline__ void ldsm4(uint32_t (&r)[4], uint32_t addr) {
    asm volatile("ldmatrix.sync.aligned.m8n8.x4.shared.b16 {%0,%1,%2,%3}, [%4];"
                 : "=r"(r[0]), "=r"(r[1]), "=r"(r[2]), "=r"(r[3]) : "r"(addr));
}
__device__ __forceinline__ void mma16816(float (&d)[4], const uint32_t (&a)[4],
                                         uint32_t b0, uint32_t b1) {
    asm volatile(
        "mma.sync.aligned.m16n8k16.row.col.f32.bf16.bf16.f32 "
        "{%0,%1,%2,%3}, {%4,%5,%6,%7}, {%8,%9}, {%0,%1,%2,%3};"
        : "+f"(d[0]), "+f"(d[1]), "+f"(d[2]), "+f"(d[3])
        : "r"(a[0]), "r"(a[1]), "r"(a[2]), "r"(a[3]), "r"(b0), "r"(b1));
}

// ---------------- tensor-core GEMM (static smem, 2 blocks/SM) ----------------
#define LDA 80

template <int K>
__global__ void __launch_bounds__(256, 2) gemm_mma_k(
    const __nv_bfloat16* __restrict__ Ah, const __nv_bfloat16* __restrict__ Al,
    const __nv_bfloat16* __restrict__ Bh, const __nv_bfloat16* __restrict__ Bl,
    float* __restrict__ C, const float* __restrict__ alw, const float* __restrict__ arw)
{
    __shared__ __align__(16) uint8_t sAh[128 * LDA];
    __shared__ __align__(16) uint8_t sAl[128 * LDA];
    __shared__ __align__(16) uint8_t sBh[128 * LDA];
    __shared__ __align__(16) uint8_t sBl[128 * LDA];

    const int t = threadIdx.x;
    const int wid = t >> 5, lane = t & 31;
    const int warp_m = wid & 3, warp_n = wid >> 2;
    const int row0 = blockIdx.y * 128;
    const int nbase = blockIdx.x * 128;

    float acc[2][8][4];
#pragma unroll
    for (int i = 0; i < 2; i++)
#pragma unroll
        for (int j = 0; j < 8; j++)
#pragma unroll
            for (int q = 0; q < 4; q++) acc[i][j][q] = 0.f;

    const uint32_t uAh = (uint32_t)__cvta_generic_to_shared(sAh);
    const uint32_t uAl = (uint32_t)__cvta_generic_to_shared(sAl);
    const uint32_t uBh = (uint32_t)__cvta_generic_to_shared(sBh);
    const uint32_t uBl = (uint32_t)__cvta_generic_to_shared(sBl);
    const uint32_t rowOff = (uint32_t)(lane & 15) * LDA + (uint32_t)((lane >> 4) << 4);
    const uint32_t aOff = (uint32_t)warp_m * 32 * LDA + rowOff;
    const uint32_t bOff = (uint32_t)warp_n * 64 * LDA + rowOff;

    const int lrow = t >> 1;
    const int lkq = (t & 1) * 16;
    const uint4 zv = make_uint4(0, 0, 0, 0);
    const int arow = row0 + lrow;
    const bool aok = arow < N_NODES;
    const int brow = nbase + lrow;

    for (int k0 = 0; k0 < K; k0 += 32) {
        {
            const __nv_bfloat16* pa = Ah + (size_t)arow * K + k0 + lkq;
            const __nv_bfloat16* pl = Al + (size_t)arow * K + k0 + lkq;
            uint8_t* da = sAh + lrow * LDA + lkq * 2;
            uint8_t* dl = sAl + lrow * LDA + lkq * 2;
            *(uint4*)(da +  0) = aok ? ((const uint4*)pa)[0] : zv;
            *(uint4*)(da + 16) = aok ? ((const uint4*)pa)[1] : zv;
            *(uint4*)(dl +  0) = aok ? ((const uint4*)pl)[0] : zv;
            *(uint4*)(dl + 16) = aok ? ((const uint4*)pl)[1] : zv;
            const __nv_bfloat16* pb = Bh + (size_t)brow * K + k0 + lkq;
            const __nv_bfloat16* pq = Bl + (size_t)brow * K + k0 + lkq;
            uint8_t* db = sBh + lrow * LDA + lkq * 2;
            uint8_t* dq = sBl + lrow * LDA + lkq * 2;
            *(uint4*)(db +  0) = ((const uint4*)pb)[0];
            *(uint4*)(db + 16) = ((const uint4*)pb)[1];
            *(uint4*)(dq +  0) = ((const uint4*)pq)[0];
            *(uint4*)(dq + 16) = ((const uint4*)pq)[1];
        }
        __syncthreads();

#pragma unroll
        for (int kk = 0; kk < 2; kk++) {
            const uint32_t kb = kk * 32;
            uint32_t aH[2][4];
#pragma unroll
            for (int mt = 0; mt < 2; mt++) ldsm4(aH[mt], uAh + aOff + mt * 16 * LDA + kb);
            {
                uint32_t bH[4][4];
#pragma unroll
                for (int p = 0; p < 4; p++) ldsm4(bH[p], uBh + bOff + p * 16 * LDA + kb);
#pragma unroll
                for (int mt = 0; mt < 2; mt++)
#pragma unroll
                    for (int p = 0; p < 4; p++) {
                        mma16816(acc[mt][2 * p + 0], aH[mt], bH[p][0], bH[p][2]);
                        mma16816(acc[mt][2 * p + 1], aH[mt], bH[p][1], bH[p][3]);
                    }
                uint32_t aL[2][4];
#pragma unroll
                for (int mt = 0; mt < 2; mt++) ldsm4(aL[mt], uAl + aOff + mt * 16 * LDA + kb);
#pragma unroll
                for (int mt = 0; mt < 2; mt++)
#pragma unroll
                    for (int p = 0; p < 4; p++) {
                        mma16816(acc[mt][2 * p + 0], aL[mt], bH[p][0], bH[p][2]);
                        mma16816(acc[mt][2 * p + 1], aL[mt], bH[p][1], bH[p][3]);
                    }
            }
            {
                uint32_t bL[4][4];
#pragma unroll
                for (int p = 0; p < 4; p++) ldsm4(bL[p], uBl + bOff + p * 16 * LDA + kb);
#pragma unroll
                for (int mt = 0; mt < 2; mt++)
#pragma unroll
                    for (int p = 0; p < 4; p++) {
                        mma16816(acc[mt][2 * p + 0], aH[mt], bL[p][0], bL[p][2]);
                        mma16816(acc[mt][2 * p + 1], aH[mt], bL[p][1], bL[p][3]);
                    }
            }
        }
        __syncthreads();
    }

    // ---- epilogue: fp32 h + fused attention scores ----
    const int g = lane >> 2;
    const int tig = lane & 3;
    const int head = blockIdx.x * 2 + warp_n;
    const int cihb = tig * 2;

#pragma unroll
    for (int mt = 0; mt < 2; mt++) {
#pragma unroll
        for (int half = 0; half < 2; half++) {
            int grow = row0 + warp_m * 32 + mt * 16 + g + half * 8;
            if (grow >= N_NODES) continue;
            float sl = 0.f, sr = 0.f;
            float* cp = C + (size_t)grow * 256 + nbase + warp_n * 64;
#pragma unroll
            for (int nt = 0; nt < 8; nt++) {
                float c0 = acc[mt][nt][half * 2 + 0];
                float c1 = acc[mt][nt][half * 2 + 1];
                int cih = nt * 8 + cihb;
                *(float2*)(cp + cih) = make_float2(c0, c1);
                sl += c0 * alw[head * 64 + cih] + c1 * alw[head * 64 + cih + 1];
                sr += c0 * arw[head * 64 + cih] + c1 * arw[head * 64 + cih + 1];
            }
            sl += __shfl_xor_sync(0xffffffffu, sl, 1);
            sl += __shfl_xor_sync(0xffffffffu, sl, 2);
            sr += __shfl_xor_sync(0xffffffffu, sr, 1);
            sr += __shfl_xor_sync(0xffffffffu, sr, 2);
            if (tig == 0) {
                g_el[grow * 4 + head] = sl;
                g_er[grow * 4 + head] = sr;
            }
        }
    }
}

// ---------------- single-pass aggregate (no max shift; scores bounded) ----------------
// LAST=false: emit bf16 hi/lo for next GEMM
// LAST=true:  fused final head -> out[v] = relu(mean_heads(o) @ Wout + bout)
template <bool LAST>
__global__ void __launch_bounds__(128) aggregate_k(const float* __restrict__ h,
                                                   float* __restrict__ out,
                                                   const float* __restrict__ Wout,
                                                   const float* __restrict__ bout, int N) {
    int v = (blockIdx.x * 128 + threadIdx.x) >> 5;
    int lane = threadIdx.x & 31;
    if (v >= N) return;
    int hd = lane >> 3;

    float4 er4 = ((const float4*)g_er)[v];
    float erv = (hd == 0) ? er4.x : (hd == 1) ? er4.y : (hd == 2) ? er4.z : er4.w;

    int r0 = g_rowptr[v];
    int r1 = g_rowptr[v + 1];

    float ssum = 0.f;
    float4 acca = make_float4(0.f, 0.f, 0.f, 0.f);
    float4 accb = make_float4(0.f, 0.f, 0.f, 0.f);

    int j = r0;
    for (; j + 2 <= r1; j += 2) {
        int s0 = g_csr_src[j];
        int s1 = g_csr_src[j + 1];
        float4 el40 = ((const float4*)g_el)[s0];
        float4 el41 = ((const float4*)g_el)[s1];
        const float4* hp0 = (const float4*)(h + (size_t)s0 * HH + lane * 8);
        const float4* hp1 = (const float4*)(h + (size_t)s1 * HH + lane * 8);
        float4 ha0 = hp0[0], hb0 = hp0[1];
        float4 ha1 = hp1[0], hb1 = hp1[1];
        float e0 = ((hd == 0) ? el40.x : (hd == 1) ? el40.y : (hd == 2) ? el40.z : el40.w) + erv;
        float e1 = ((hd == 0) ? el41.x : (hd == 1) ? el41.y : (hd == 2) ? el41.z : el41.w) + erv;
        e0 = (e0 > 0.f) ? e0 : 0.2f * e0;
        e1 = (e1 > 0.f) ? e1 : 0.2f * e1;
        float w0 = __expf(e0);
        float w1 = __expf(e1);
        ssum += w0 + w1;
        acca.x = fmaf(w0, ha0.x, fmaf(w1, ha1.x, acca.x));
        acca.y = fmaf(w0, ha0.y, fmaf(w1, ha1.y, acca.y));
        acca.z = fmaf(w0, ha0.z, fmaf(w1, ha1.z, acca.z));
        acca.w = fmaf(w0, ha0.w, fmaf(w1, ha1.w, acca.w));
        accb.x = fmaf(w0, hb0.x, fmaf(w1, hb1.x, accb.x));
        accb.y = fmaf(w0, hb0.y, fmaf(w1, hb1.y, accb.y));
        accb.z = fmaf(w0, hb0.z, fmaf(w1, hb1.z, accb.z));
        accb.w = fmaf(w0, hb0.w, fmaf(w1, hb1.w, accb.w));
    }
    if (j < r1) {
        int s0 = g_csr_src[j];
        float4 el40 = ((const float4*)g_el)[s0];
        const float4* hp0 = (const float4*)(h + (size_t)s0 * HH + lane * 8);
        float4 ha0 = hp0[0], hb0 = hp0[1];
        float e0 = ((hd == 0) ? el40.x : (hd == 1) ? el40.y : (hd == 2) ? el40.z : el40.w) + erv;
        e0 = (e0 > 0.f) ? e0 : 0.2f * e0;
        float w0 = __expf(e0);
        ssum += w0;
        acca.x = fmaf(w0, ha0.x, acca.x);
        acca.y = fmaf(w0, ha0.y, acca.y);
        acca.z = fmaf(w0, ha0.z, acca.z);
        acca.w = fmaf(w0, ha0.w, acca.w);
        accb.x = fmaf(w0, hb0.x, accb.x);
        accb.y = fmaf(w0, hb0.y, accb.y);
        accb.z = fmaf(w0, hb0.z, accb.z);
        accb.w = fmaf(w0, hb0.w, accb.w);
    }

    float inv = 1.f / (ssum + 1e-9f);
    float o[8] = {acca.x * inv, acca.y * inv, acca.z * inv, acca.w * inv,
                  accb.x * inv, accb.y * inv, accb.z * inv, accb.w * inv};
#pragma unroll
    for (int i = 0; i < 8; i++) o[i] = (o[i] > 0.f) ? o[i] : expm1f(o[i]);

    if (LAST) {
        const int dbase = (lane & 7) * 8;
        float s = 0.f;
#pragma unroll
        for (int i = 0; i < 8; i++) s += o[i] * Wout[dbase + i];
#pragma unroll
        for (int off = 16; off >= 1; off >>= 1) s += __shfl_xor_sync(0xffffffffu, s, off);
        if (lane == 0) {
            float r = 0.25f * s + bout[0];
            out[v] = (r > 0.f) ? r : 0.f;
        }
    } else {
        __nv_bfloat16 hi[8], lo[8];
#pragma unroll
        for (int i = 0; i < 8; i++) {
            hi[i] = __float2bfloat16(o[i]);
            lo[i] = __float2bfloat16(o[i] - __bfloat162float(hi[i]));
        }
        *(uint4*)(g_a_hi + (size_t)v * 256 + lane * 8) = *(const uint4*)hi;
        *(uint4*)(g_a_lo + (size_t)v * 256 + lane * 8) = *(const uint4*)lo;
    }
}

// ---------------- launch ----------------
extern "C" void kernel_launch(void* const* d_in, const int* in_sizes, int n_in,
                              void* d_out, int out_size) {
    const float* x    = (const float*)d_in[0];
    const int*   src  = (const int*)d_in[1];
    const int*   dst  = (const int*)d_in[2];
    const float* W0   = (const float*)d_in[3];
    const float* al0  = (const float*)d_in[4];
    const float* ar0  = (const float*)d_in[5];
    const float* W1   = (const float*)d_in[6];
    const float* al1  = (const float*)d_in[7];
    const float* ar1  = (const float*)d_in[8];
    const float* W2   = (const float*)d_in[9];
    const float* al2  = (const float*)d_in[10];
    const float* ar2  = (const float*)d_in[11];
    const float* Wout = (const float*)d_in[12];
    const float* bout = (const float*)d_in[13];

    const int N = N_NODES;
    const int E = N_EDGES;

    float *h;
    __nv_bfloat16 *ah, *al, *wh, *wl;
    cudaGetSymbolAddress((void**)&h, g_h);
    cudaGetSymbolAddress((void**)&ah, g_a_hi);
    cudaGetSymbolAddress((void**)&al, g_a_lo);
    cudaGetSymbolAddress((void**)&wh, g_w_hi);
    cudaGetSymbolAddress((void**)&wl, g_w_lo);

    dim3 ggrid(2, (N + 127) / 128);
    const int warpGrid = (N + 3) / 4;
    const int wtotal = 128 * 256 + 2 * 256 * 256;

    // (1) convert x + zero counts
    convert_x_k<<<(N * 128 + 255) / 256, 256>>>(x, N * 128);
    // (2) convert all weights
    convert_w_all_k<<<(wtotal + 255) / 256, 256>>>(W0, W1, W2);
    // (3) histogram
    hist_k<<<(E + 255) / 256, 256>>>(dst, E);
    // (4) scan (+ zero cursors)
    scan_k<<<1, 1024>>>();
    // (5) scatter
    scatter_k<<<(E + 255) / 256, 256>>>(src, dst, E);
    // (6) layer-0 GEMM (independent of CSR — placed here so ncu's profiled slot lands on it)
    gemm_mma_k<128><<<ggrid, 256>>>(ah, al, wh + 0 * 65536, wl + 0 * 65536, h, al0, ar0);
    // (7..) rest of the pipeline
    aggregate_k<false><<<warpGrid, 128>>>(h, nullptr, nullptr, nullptr, N);
    gemm_mma_k<256><<<ggrid, 256>>>(ah, al, wh + 1 * 65536, wl + 1 * 65536, h, al1, ar1);
    aggregate_k<false><<<warpGrid, 128>>>(h, nullptr, nullptr, nullptr, N);
    gemm_mma_k<256><<<ggrid, 256>>>(ah, al, wh + 2 * 65536, wl + 2 * 65536, h, al2, ar2);
    aggregate_k<true><<<warpGrid, 128>>>(h, (float*)d_out, Wout, bout, N);
}

// round 8
// speedup vs baseline: 1.2798x; 1.1520x over previous
#include <cuda_runtime.h>
#include <cuda_bf16.h>
#include <math.h>
#include <stdint.h>

#define N_NODES 50000
#define N_EDGES 800000
#define HH 256
#define NHEADS 4
#define MPAD 50048
#define NBLK 196          // ceil(N_NODES/256)

// ---------------- scratch ----------------
__device__ float g_h  [(size_t)N_NODES * HH];   // GEMM output (fp32 message payload)
__device__ float g_el [N_NODES * NHEADS];
__device__ float g_er [N_NODES * NHEADS];
__device__ int   g_rowptr[N_NODES + 1];
__device__ int   g_counts[N_NODES];
__device__ int   g_csr_src[N_EDGES];
__device__ int   g_part[NBLK];
__device__ int   g_partoff[NBLK];
__device__ __nv_bfloat16 g_a_hi[(size_t)MPAD * 256];
__device__ __nv_bfloat16 g_a_lo[(size_t)MPAD * 256];
__device__ __nv_bfloat16 g_w_hi[3 * 256 * 256];   // W^T per layer, [n][k]
__device__ __nv_bfloat16 g_w_lo[3 * 256 * 256];

// ---------------- conversions (+ fused count zeroing) ----------------
__global__ void convert_x_k(const float* __restrict__ x, int total) {
    int i = blockIdx.x * blockDim.x + threadIdx.x;
    if (i < N_NODES) g_counts[i] = 0;   // fused: zero histogram counters
    if (i >= total) return;
    float a = x[i];
    __nv_bfloat16 hi = __float2bfloat16(a);
    __nv_bfloat16 lo = __float2bfloat16(a - __bfloat162float(hi));
    g_a_hi[i] = hi;
    g_a_lo[i] = lo;
}

__global__ void convert_w_all_k(const float* __restrict__ W0,
                                const float* __restrict__ W1,
                                const float* __restrict__ W2) {
    int i = blockIdx.x * blockDim.x + threadIdx.x;
    const float* W;
    __nv_bfloat16 *oh, *ol;
    int K, idx;
    if (i < 128 * 256) {
        W = W0; K = 128; idx = i;
        oh = g_w_hi + 0 * 65536; ol = g_w_lo + 0 * 65536;
    } else if (i < 128 * 256 + 256 * 256) {
        W = W1; K = 256; idx = i - 128 * 256;
        oh = g_w_hi + 1 * 65536; ol = g_w_lo + 1 * 65536;
    } else if (i < 128 * 256 + 2 * 256 * 256) {
        W = W2; K = 256; idx = i - 128 * 256 - 256 * 256;
        oh = g_w_hi + 2 * 65536; ol = g_w_lo + 2 * 65536;
    } else return;
    int k = idx / 256, n = idx % 256;
    float a = W[idx];
    __nv_bfloat16 hi = __float2bfloat16(a);
    __nv_bfloat16 lo = __float2bfloat16(a - __bfloat162float(hi));
    oh[(size_t)n * K + k] = hi;
    ol[(size_t)n * K + k] = lo;
}

// ---------------- CSR build ----------------
__global__ void hist_k(const int* __restrict__ dst, int E) {
    int i = blockIdx.x * blockDim.x + threadIdx.x;
    if (i < E) atomicAdd(&g_counts[dst[i]], 1);
}

// hierarchical scan, stage 1: per-block sums of 256 counts
__global__ void partial_k() {
    __shared__ int sh[256];
    int b = blockIdx.x, t = threadIdx.x;
    int i = b * 256 + t;
    sh[t] = (i < N_NODES) ? g_counts[i] : 0;
    __syncthreads();
#pragma unroll
    for (int off = 128; off >= 1; off >>= 1) {
        if (t < off) sh[t] += sh[t + off];
        __syncthreads();
    }
    if (t == 0) g_part[b] = sh[0];
}

// stage 2: scan the 196 block sums (single tiny block)
__global__ void scanpart_k() {
    __shared__ int sh[256];
    int t = threadIdx.x;
    int v = (t < NBLK) ? g_part[t] : 0;
    sh[t] = v;
    __syncthreads();
#pragma unroll
    for (int off = 1; off < 256; off <<= 1) {
        int u = (t >= off) ? sh[t - off] : 0;
        __syncthreads();
        sh[t] += u;
        __syncthreads();
    }
    if (t < NBLK) g_partoff[t] = sh[t] - v;   // exclusive
    if (t == NBLK - 1) g_rowptr[N_NODES] = sh[t];
}

// stage 3: per-block exclusive scan + offset -> rowptr; reset cursors
__global__ void rowptr_k() {
    __shared__ int sh[256];
    int b = blockIdx.x, t = threadIdx.x;
    int i = b * 256 + t;
    int v = (i < N_NODES) ? g_counts[i] : 0;
    sh[t] = v;
    __syncthreads();
#pragma unroll
    for (int off = 1; off < 256; off <<= 1) {
        int u = (t >= off) ? sh[t - off] : 0;
        __syncthreads();
        sh[t] += u;
        __syncthreads();
    }
    if (i < N_NODES) {
        g_rowptr[i] = g_partoff[b] + sh[t] - v;   // exclusive
        g_counts[i] = 0;                          // reset cursor for scatter
    }
}

__global__ void scatter_k(const int* __restrict__ src, const int* __restrict__ dst, int E) {
    int i = blockIdx.x * blockDim.x + threadIdx.x;
    if (i < E) {
        int d = dst[i];
        int pos = g_rowptr[d] + atomicAdd(&g_counts[d], 1);
        g_csr_src[pos] = src[i];
    }
}

// ---------------- warp-MMA helpers ----------------
__device__ __forceinline__ void ldsm4(uint32_t (&r)[4], uint32_t addr) {
    asm volatile("ldmatrix.sync.aligned.m8n8.x4.shared.b16 {%0,%1,%2,%3}, [%4];"
                 : "=r"(r[0]), "=r"(r[1]), "=r"(r[2]), "=r"(r[3]) : "r"(addr));
}
__device__ __forceinline__ void mma16816(float (&d)[4], const uint32_t (&a)[4],
                                         uint32_t b0, uint32_t b1) {
    asm volatile(
        "mma.sync.aligned.m16n8k16.row.col.f32.bf16.bf16.f32 "
        "{%0,%1,%2,%3}, {%4,%5,%6,%7}, {%8,%9}, {%0,%1,%2,%3};"
        : "+f"(d[0]), "+f"(d[1]), "+f"(d[2]), "+f"(d[3])
        : "r"(a[0]), "r"(a[1]), "r"(a[2]), "r"(a[3]), "r"(b0), "r"(b1));
}

// ---------------- tensor-core GEMM (static smem, 2 blocks/SM) ----------------
#define LDA 80

template <int K>
__global__ void __launch_bounds__(256, 2) gemm_mma_k(
    const __nv_bfloat16* __restrict__ Ah, const __nv_bfloat16* __restrict__ Al,
    const __nv_bfloat16* __restrict__ Bh, const __nv_bfloat16* __restrict__ Bl,
    float* __restrict__ C, const float* __restrict__ alw, const float* __restrict__ arw)
{
    __shared__ __align__(16) uint8_t sAh[128 * LDA];
    __shared__ __align__(16) uint8_t sAl[128 * LDA];
    __shared__ __align__(16) uint8_t sBh[128 * LDA];
    __shared__ __align__(16) uint8_t sBl[128 * LDA];

    const int t = threadIdx.x;
    const int wid = t >> 5, lane = t & 31;
    const int warp_m = wid & 3, warp_n = wid >> 2;
    const int row0 = blockIdx.y * 128;
    const int nbase = blockIdx.x * 128;

    float acc[2][8][4];
#pragma unroll
    for (int i = 0; i < 2; i++)
#pragma unroll
        for (int j = 0; j < 8; j++)
#pragma unroll
            for (int q = 0; q < 4; q++) acc[i][j][q] = 0.f;

    const uint32_t uAh = (uint32_t)__cvta_generic_to_shared(sAh);
    const uint32_t uAl = (uint32_t)__cvta_generic_to_shared(sAl);
    const uint32_t uBh = (uint32_t)__cvta_generic_to_shared(sBh);
    const uint32_t uBl = (uint32_t)__cvta_generic_to_shared(sBl);
    const uint32_t rowOff = (uint32_t)(lane & 15) * LDA + (uint32_t)((lane >> 4) << 4);
    const uint32_t aOff = (uint32_t)warp_m * 32 * LDA + rowOff;
    const uint32_t bOff = (uint32_t)warp_n * 64 * LDA + rowOff;

    const int lrow = t >> 1;
    const int lkq = (t & 1) * 16;
    const uint4 zv = make_uint4(0, 0, 0, 0);
    const int arow = row0 + lrow;
    const bool aok = arow < N_NODES;
    const int brow = nbase + lrow;

    for (int k0 = 0; k0 < K; k0 += 32) {
        {
            const __nv_bfloat16* pa = Ah + (size_t)arow * K + k0 + lkq;
            const __nv_bfloat16* pl = Al + (size_t)arow * K + k0 + lkq;
            uint8_t* da = sAh + lrow * LDA + lkq * 2;
            uint8_t* dl = sAl + lrow * LDA + lkq * 2;
            *(uint4*)(da +  0) = aok ? ((const uint4*)pa)[0] : zv;
            *(uint4*)(da + 16) = aok ? ((const uint4*)pa)[1] : zv;
            *(uint4*)(dl +  0) = aok ? ((const uint4*)pl)[0] : zv;
            *(uint4*)(dl + 16) = aok ? ((const uint4*)pl)[1] : zv;
            const __nv_bfloat16* pb = Bh + (size_t)brow * K + k0 + lkq;
            const __nv_bfloat16* pq = Bl + (size_t)brow * K + k0 + lkq;
            uint8_t* db = sBh + lrow * LDA + lkq * 2;
            uint8_t* dq = sBl + lrow * LDA + lkq * 2;
            *(uint4*)(db +  0) = ((const uint4*)pb)[0];
            *(uint4*)(db + 16) = ((const uint4*)pb)[1];
            *(uint4*)(dq +  0) = ((const uint4*)pq)[0];
            *(uint4*)(dq + 16) = ((const uint4*)pq)[1];
        }
        __syncthreads();

#pragma unroll
        for (int kk = 0; kk < 2; kk++) {
            const uint32_t kb = kk * 32;
            uint32_t aH[2][4];
#pragma unroll
            for (int mt = 0; mt < 2; mt++) ldsm4(aH[mt], uAh + aOff + mt * 16 * LDA + kb);
            {
                uint32_t bH[4][4];
#pragma unroll
                for (int p = 0; p < 4; p++) ldsm4(bH[p], uBh + bOff + p * 16 * LDA + kb);
#pragma unroll
                for (int mt = 0; mt < 2; mt++)
#pragma unroll
                    for (int p = 0; p < 4; p++) {
                        mma16816(acc[mt][2 * p + 0], aH[mt], bH[p][0], bH[p][2]);
                        mma16816(acc[mt][2 * p + 1], aH[mt], bH[p][1], bH[p][3]);
                    }
                uint32_t aL[2][4];
#pragma unroll
                for (int mt = 0; mt < 2; mt++) ldsm4(aL[mt], uAl + aOff + mt * 16 * LDA + kb);
#pragma unroll
                for (int mt = 0; mt < 2; mt++)
#pragma unroll
                    for (int p = 0; p < 4; p++) {
                        mma16816(acc[mt][2 * p + 0], aL[mt], bH[p][0], bH[p][2]);
                        mma16816(acc[mt][2 * p + 1], aL[mt], bH[p][1], bH[p][3]);
                    }
            }
            {
                uint32_t bL[4][4];
#pragma unroll
                for (int p = 0; p < 4; p++) ldsm4(bL[p], uBl + bOff + p * 16 * LDA + kb);
#pragma unroll
                for (int mt = 0; mt < 2; mt++)
#pragma unroll
                    for (int p = 0; p < 4; p++) {
                        mma16816(acc[mt][2 * p + 0], aH[mt], bL[p][0], bL[p][2]);
                        mma16816(acc[mt][2 * p + 1], aH[mt], bL[p][1], bL[p][3]);
                    }
            }
        }
        __syncthreads();
    }

    // ---- epilogue: fp32 h + fused attention scores ----
    const int g = lane >> 2;
    const int tig = lane & 3;
    const int head = blockIdx.x * 2 + warp_n;
    const int cihb = tig * 2;

#pragma unroll
    for (int mt = 0; mt < 2; mt++) {
#pragma unroll
        for (int half = 0; half < 2; half++) {
            int grow = row0 + warp_m * 32 + mt * 16 + g + half * 8;
            if (grow >= N_NODES) continue;
            float sl = 0.f, sr = 0.f;
            float* cp = C + (size_t)grow * 256 + nbase + warp_n * 64;
#pragma unroll
            for (int nt = 0; nt < 8; nt++) {
                float c0 = acc[mt][nt][half * 2 + 0];
                float c1 = acc[mt][nt][half * 2 + 1];
                int cih = nt * 8 + cihb;
                *(float2*)(cp + cih) = make_float2(c0, c1);
                sl += c0 * alw[head * 64 + cih] + c1 * alw[head * 64 + cih + 1];
                sr += c0 * arw[head * 64 + cih] + c1 * arw[head * 64 + cih + 1];
            }
            sl += __shfl_xor_sync(0xffffffffu, sl, 1);
            sl += __shfl_xor_sync(0xffffffffu, sl, 2);
            sr += __shfl_xor_sync(0xffffffffu, sr, 1);
            sr += __shfl_xor_sync(0xffffffffu, sr, 2);
            if (tig == 0) {
                g_el[grow * 4 + head] = sl;
                g_er[grow * 4 + head] = sr;
            }
        }
    }
}

// ---------------- single-pass aggregate (no max shift; scores bounded) ----------------
template <bool LAST>
__global__ void __launch_bounds__(128) aggregate_k(const float* __restrict__ h,
                                                   float* __restrict__ out,
                                                   const float* __restrict__ Wout,
                                                   const float* __restrict__ bout, int N) {
    int v = (blockIdx.x * 128 + threadIdx.x) >> 5;
    int lane = threadIdx.x & 31;
    if (v >= N) return;
    int hd = lane >> 3;

    float4 er4 = ((const float4*)g_er)[v];
    float erv = (hd == 0) ? er4.x : (hd == 1) ? er4.y : (hd == 2) ? er4.z : er4.w;

    int r0 = g_rowptr[v];
    int r1 = g_rowptr[v + 1];

    float ssum = 0.f;
    float4 acca = make_float4(0.f, 0.f, 0.f, 0.f);
    float4 accb = make_float4(0.f, 0.f, 0.f, 0.f);

    int j = r0;
    for (; j + 2 <= r1; j += 2) {
        int s0 = g_csr_src[j];
        int s1 = g_csr_src[j + 1];
        float4 el40 = ((const float4*)g_el)[s0];
        float4 el41 = ((const float4*)g_el)[s1];
        const float4* hp0 = (const float4*)(h + (size_t)s0 * HH + lane * 8);
        const float4* hp1 = (const float4*)(h + (size_t)s1 * HH + lane * 8);
        float4 ha0 = hp0[0], hb0 = hp0[1];
        float4 ha1 = hp1[0], hb1 = hp1[1];
        float e0 = ((hd == 0) ? el40.x : (hd == 1) ? el40.y : (hd == 2) ? el40.z : el40.w) + erv;
        float e1 = ((hd == 0) ? el41.x : (hd == 1) ? el41.y : (hd == 2) ? el41.z : el41.w) + erv;
        e0 = (e0 > 0.f) ? e0 : 0.2f * e0;
        e1 = (e1 > 0.f) ? e1 : 0.2f * e1;
        float w0 = __expf(e0);
        float w1 = __expf(e1);
        ssum += w0 + w1;
        acca.x = fmaf(w0, ha0.x, fmaf(w1, ha1.x, acca.x));
        acca.y = fmaf(w0, ha0.y, fmaf(w1, ha1.y, acca.y));
        acca.z = fmaf(w0, ha0.z, fmaf(w1, ha1.z, acca.z));
        acca.w = fmaf(w0, ha0.w, fmaf(w1, ha1.w, acca.w));
        accb.x = fmaf(w0, hb0.x, fmaf(w1, hb1.x, accb.x));
        accb.y = fmaf(w0, hb0.y, fmaf(w1, hb1.y, accb.y));
        accb.z = fmaf(w0, hb0.z, fmaf(w1, hb1.z, accb.z));
        accb.w = fmaf(w0, hb0.w, fmaf(w1, hb1.w, accb.w));
    }
    if (j < r1) {
        int s0 = g_csr_src[j];
        float4 el40 = ((const float4*)g_el)[s0];
        const float4* hp0 = (const float4*)(h + (size_t)s0 * HH + lane * 8);
        float4 ha0 = hp0[0], hb0 = hp0[1];
        float e0 = ((hd == 0) ? el40.x : (hd == 1) ? el40.y : (hd == 2) ? el40.z : el40.w) + erv;
        e0 = (e0 > 0.f) ? e0 : 0.2f * e0;
        float w0 = __expf(e0);
        ssum += w0;
        acca.x = fmaf(w0, ha0.x, acca.x);
        acca.y = fmaf(w0, ha0.y, acca.y);
        acca.z = fmaf(w0, ha0.z, acca.z);
        acca.w = fmaf(w0, ha0.w, acca.w);
        accb.x = fmaf(w0, hb0.x, accb.x);
        accb.y = fmaf(w0, hb0.y, accb.y);
        accb.z = fmaf(w0, hb0.z, accb.z);
        accb.w = fmaf(w0, hb0.w, accb.w);
    }

    float inv = 1.f / (ssum + 1e-9f);
    float o[8] = {acca.x * inv, acca.y * inv, acca.z * inv, acca.w * inv,
                  accb.x * inv, accb.y * inv, accb.z * inv, accb.w * inv};
#pragma unroll
    for (int i = 0; i < 8; i++) o[i] = (o[i] > 0.f) ? o[i] : expm1f(o[i]);

    if (LAST) {
        const int dbase = (lane & 7) * 8;
        float s = 0.f;
#pragma unroll
        for (int i = 0; i < 8; i++) s += o[i] * Wout[dbase + i];
#pragma unroll
        for (int off = 16; off >= 1; off >>= 1) s += __shfl_xor_sync(0xffffffffu, s, off);
        if (lane == 0) {
            float r = 0.25f * s + bout[0];
            out[v] = (r > 0.f) ? r : 0.f;
        }
    } else {
        __nv_bfloat16 hi[8], lo[8];
#pragma unroll
        for (int i = 0; i < 8; i++) {
            hi[i] = __float2bfloat16(o[i]);
            lo[i] = __float2bfloat16(o[i] - __bfloat162float(hi[i]));
        }
        *(uint4*)(g_a_hi + (size_t)v * 256 + lane * 8) = *(const uint4*)hi;
        *(uint4*)(g_a_lo + (size_t)v * 256 + lane * 8) = *(const uint4*)lo;
    }
}

// ---------------- launch ----------------
extern "C" void kernel_launch(void* const* d_in, const int* in_sizes, int n_in,
                              void* d_out, int out_size) {
    const float* x    = (const float*)d_in[0];
    const int*   src  = (const int*)d_in[1];
    const int*   dst  = (const int*)d_in[2];
    const float* W0   = (const float*)d_in[3];
    const float* al0  = (const float*)d_in[4];
    const float* ar0  = (const float*)d_in[5];
    const float* W1   = (const float*)d_in[6];
    const float* al1  = (const float*)d_in[7];
    const float* ar1  = (const float*)d_in[8];
    const float* W2   = (const float*)d_in[9];
    const float* al2  = (const float*)d_in[10];
    const float* ar2  = (const float*)d_in[11];
    const float* Wout = (const float*)d_in[12];
    const float* bout = (const float*)d_in[13];

    const int N = N_NODES;
    const int E = N_EDGES;

    float *h;
    __nv_bfloat16 *ah, *al, *wh, *wl;
    cudaGetSymbolAddress((void**)&h, g_h);
    cudaGetSymbolAddress((void**)&ah, g_a_hi);
    cudaGetSymbolAddress((void**)&al, g_a_lo);
    cudaGetSymbolAddress((void**)&wh, g_w_hi);
    cudaGetSymbolAddress((void**)&wl, g_w_lo);

    dim3 ggrid(2, (N + 127) / 128);
    const int warpGrid = (N + 3) / 4;
    const int wtotal = 128 * 256 + 2 * 256 * 256;

    convert_x_k<<<(N * 128 + 255) / 256, 256>>>(x, N * 128);
    convert_w_all_k<<<(wtotal + 255) / 256, 256>>>(W0, W1, W2);
    hist_k<<<(E + 255) / 256, 256>>>(dst, E);
    // hierarchical scan (replaces 84us single-block scan)
    partial_k<<<NBLK, 256>>>();
    scanpart_k<<<1, 256>>>();
    rowptr_k<<<NBLK, 256>>>();
    scatter_k<<<(E + 255) / 256, 256>>>(src, dst, E);
    // layer 0 (K=128)
    gemm_mma_k<128><<<ggrid, 256>>>(ah, al, wh + 0 * 65536, wl + 0 * 65536, h, al0, ar0);
    aggregate_k<false><<<warpGrid, 128>>>(h, nullptr, nullptr, nullptr, N);
    // layer 1 (K=256)
    gemm_mma_k<256><<<ggrid, 256>>>(ah, al, wh + 1 * 65536, wl + 1 * 65536, h, al1, ar1);
    aggregate_k<false><<<warpGrid, 128>>>(h, nullptr, nullptr, nullptr, N);
    // layer 2 (K=256) + fused final head
    gemm_mma_k<256><<<ggrid, 256>>>(ah, al, wh + 2 * 65536, wl + 2 * 65536, h, al2, ar2);
    aggregate_k<true><<<warpGrid, 128>>>(h, (float*)d_out, Wout, bout, N);
}

// round 9
// speedup vs baseline: 1.3287x; 1.0382x over previous
#include <cuda_runtime.h>
#include <cuda_bf16.h>
#include <math.h>
#include <stdint.h>

#define N_NODES 50000
#define N_EDGES 800000
#define HH 256
#define NHEADS 4
#define MPAD 50048
#define NBLK 196          // ceil(N_NODES/256)

// ---------------- scratch ----------------
__device__ float g_h  [(size_t)N_NODES * HH];   // GEMM output (fp32 message payload)
__device__ float g_el [N_NODES * NHEADS];
__device__ float g_er [N_NODES * NHEADS];
__device__ int   g_rowptr[N_NODES + 1];
__device__ int   g_counts[N_NODES];
__device__ int   g_csr_src[N_EDGES];
__device__ int   g_part[NBLK];
__device__ int   g_partoff[NBLK];
__device__ __nv_bfloat16 g_a_hi[(size_t)MPAD * 256];
__device__ __nv_bfloat16 g_a_lo[(size_t)MPAD * 256];
__device__ __nv_bfloat16 g_w_hi[3 * 256 * 256];   // W^T per layer, [n][k]
__device__ __nv_bfloat16 g_w_lo[3 * 256 * 256];

// ---------------- weight conversion (+ fused count zeroing) ----------------
__global__ void convert_w_all_k(const float* __restrict__ W0,
                                const float* __restrict__ W1,
                                const float* __restrict__ W2) {
    int i = blockIdx.x * blockDim.x + threadIdx.x;
    if (i < N_NODES) g_counts[i] = 0;   // fused: zero histogram counters
    const float* W;
    __nv_bfloat16 *oh, *ol;
    int K, idx;
    if (i < 128 * 256) {
        W = W0; K = 128; idx = i;
        oh = g_w_hi + 0 * 65536; ol = g_w_lo + 0 * 65536;
    } else if (i < 128 * 256 + 256 * 256) {
        W = W1; K = 256; idx = i - 128 * 256;
        oh = g_w_hi + 1 * 65536; ol = g_w_lo + 1 * 65536;
    } else if (i < 128 * 256 + 2 * 256 * 256) {
        W = W2; K = 256; idx = i - 128 * 256 - 256 * 256;
        oh = g_w_hi + 2 * 65536; ol = g_w_lo + 2 * 65536;
    } else return;
    int k = idx / 256, n = idx % 256;
    float a = W[idx];
    __nv_bfloat16 hi = __float2bfloat16(a);
    __nv_bfloat16 lo = __float2bfloat16(a - __bfloat162float(hi));
    oh[(size_t)n * K + k] = hi;
    ol[(size_t)n * K + k] = lo;
}

// ---------------- CSR build ----------------
__global__ void hist_k(const int* __restrict__ dst, int E) {
    int i = blockIdx.x * blockDim.x + threadIdx.x;
    if (i < E) atomicAdd(&g_counts[dst[i]], 1);
}

__global__ void partial_k() {
    __shared__ int sh[256];
    int b = blockIdx.x, t = threadIdx.x;
    int i = b * 256 + t;
    sh[t] = (i < N_NODES) ? g_counts[i] : 0;
    __syncthreads();
#pragma unroll
    for (int off = 128; off >= 1; off >>= 1) {
        if (t < off) sh[t] += sh[t + off];
        __syncthreads();
    }
    if (t == 0) g_part[b] = sh[0];
}

__global__ void scanpart_k() {
    __shared__ int sh[256];
    int t = threadIdx.x;
    int v = (t < NBLK) ? g_part[t] : 0;
    sh[t] = v;
    __syncthreads();
#pragma unroll
    for (int off = 1; off < 256; off <<= 1) {
        int u = (t >= off) ? sh[t - off] : 0;
        __syncthreads();
        sh[t] += u;
        __syncthreads();
    }
    if (t < NBLK) g_partoff[t] = sh[t] - v;
    if (t == NBLK - 1) g_rowptr[N_NODES] = sh[t];
}

__global__ void rowptr_k() {
    __shared__ int sh[256];
    int b = blockIdx.x, t = threadIdx.x;
    int i = b * 256 + t;
    int v = (i < N_NODES) ? g_counts[i] : 0;
    sh[t] = v;
    __syncthreads();
#pragma unroll
    for (int off = 1; off < 256; off <<= 1) {
        int u = (t >= off) ? sh[t - off] : 0;
        __syncthreads();
        sh[t] += u;
        __syncthreads();
    }
    if (i < N_NODES) {
        g_rowptr[i] = g_partoff[b] + sh[t] - v;
        g_counts[i] = 0;
    }
}

__global__ void scatter_k(const int* __restrict__ src, const int* __restrict__ dst, int E) {
    int i = blockIdx.x * blockDim.x + threadIdx.x;
    if (i < E) {
        int d = dst[i];
        int pos = g_rowptr[d] + atomicAdd(&g_counts[d], 1);
        g_csr_src[pos] = src[i];
    }
}

// ---------------- warp-MMA helpers ----------------
__device__ __forceinline__ void ldsm4(uint32_t (&r)[4], uint32_t addr) {
    asm volatile("ldmatrix.sync.aligned.m8n8.x4.shared.b16 {%0,%1,%2,%3}, [%4];"
                 : "=r"(r[0]), "=r"(r[1]), "=r"(r[2]), "=r"(r[3]) : "r"(addr));
}
__device__ __forceinline__ void mma16816(float (&d)[4], const uint32_t (&a)[4],
                                         uint32_t b0, uint32_t b1) {
    asm volatile(
        "mma.sync.aligned.m16n8k16.row.col.f32.bf16.bf16.f32 "
        "{%0,%1,%2,%3}, {%4,%5,%6,%7}, {%8,%9}, {%0,%1,%2,%3};"
        : "+f"(d[0]), "+f"(d[1]), "+f"(d[2]), "+f"(d[3])
        : "r"(a[0]), "r"(a[1]), "r"(a[2]), "r"(a[3]), "r"(b0), "r"(b1));
}

// ---------------- tensor-core GEMM (static smem, 2 blocks/SM) ----------------
// AFP32: stage A from fp32 source, splitting to bf16 hi/lo on the fly (layer 0)
#define LDA 80

template <int K, bool AFP32>
__global__ void __launch_bounds__(256, 2) gemm_mma_k(
    const float* __restrict__ Afp,
    const __nv_bfloat16* __restrict__ Ah, const __nv_bfloat16* __restrict__ Al,
    const __nv_bfloat16* __restrict__ Bh, const __nv_bfloat16* __restrict__ Bl,
    float* __restrict__ C, const float* __restrict__ alw, const float* __restrict__ arw)
{
    __shared__ __align__(16) uint8_t sAh[128 * LDA];
    __shared__ __align__(16) uint8_t sAl[128 * LDA];
    __shared__ __align__(16) uint8_t sBh[128 * LDA];
    __shared__ __align__(16) uint8_t sBl[128 * LDA];

    const int t = threadIdx.x;
    const int wid = t >> 5, lane = t & 31;
    const int warp_m = wid & 3, warp_n = wid >> 2;
    const int row0 = blockIdx.y * 128;
    const int nbase = blockIdx.x * 128;

    float acc[2][8][4];
#pragma unroll
    for (int i = 0; i < 2; i++)
#pragma unroll
        for (int j = 0; j < 8; j++)
#pragma unroll
            for (int q = 0; q < 4; q++) acc[i][j][q] = 0.f;

    const uint32_t uAh = (uint32_t)__cvta_generic_to_shared(sAh);
    const uint32_t uAl = (uint32_t)__cvta_generic_to_shared(sAl);
    const uint32_t uBh = (uint32_t)__cvta_generic_to_shared(sBh);
    const uint32_t uBl = (uint32_t)__cvta_generic_to_shared(sBl);
    const uint32_t rowOff = (uint32_t)(lane & 15) * LDA + (uint32_t)((lane >> 4) << 4);
    const uint32_t aOff = (uint32_t)warp_m * 32 * LDA + rowOff;
    const uint32_t bOff = (uint32_t)warp_n * 64 * LDA + rowOff;

    const int lrow = t >> 1;
    const int lkq = (t & 1) * 16;
    const uint4 zv = make_uint4(0, 0, 0, 0);
    const int arow = row0 + lrow;
    const bool aok = arow < N_NODES;
    const int brow = nbase + lrow;

    for (int k0 = 0; k0 < K; k0 += 32) {
        {
            uint8_t* da = sAh + lrow * LDA + lkq * 2;
            uint8_t* dl = sAl + lrow * LDA + lkq * 2;
            if (AFP32) {
                // stage 16 fp32 elems -> bf16 hi/lo
                const float* pa32 = Afp + (size_t)arow * K + k0 + lkq;
                float f[16];
#pragma unroll
                for (int q = 0; q < 4; q++) {
                    float4 v = aok ? ((const float4*)pa32)[q] : make_float4(0.f, 0.f, 0.f, 0.f);
                    f[q * 4 + 0] = v.x; f[q * 4 + 1] = v.y;
                    f[q * 4 + 2] = v.z; f[q * 4 + 3] = v.w;
                }
                __nv_bfloat16 hi[16], lo[16];
#pragma unroll
                for (int q = 0; q < 16; q++) {
                    hi[q] = __float2bfloat16(f[q]);
                    lo[q] = __float2bfloat16(f[q] - __bfloat162float(hi[q]));
                }
                *(uint4*)(da +  0) = ((const uint4*)hi)[0];
                *(uint4*)(da + 16) = ((const uint4*)hi)[1];
                *(uint4*)(dl +  0) = ((const uint4*)lo)[0];
                *(uint4*)(dl + 16) = ((const uint4*)lo)[1];
            } else {
                const __nv_bfloat16* pa = Ah + (size_t)arow * K + k0 + lkq;
                const __nv_bfloat16* pl = Al + (size_t)arow * K + k0 + lkq;
                *(uint4*)(da +  0) = aok ? ((const uint4*)pa)[0] : zv;
                *(uint4*)(da + 16) = aok ? ((const uint4*)pa)[1] : zv;
                *(uint4*)(dl +  0) = aok ? ((const uint4*)pl)[0] : zv;
                *(uint4*)(dl + 16) = aok ? ((const uint4*)pl)[1] : zv;
            }
            const __nv_bfloat16* pb = Bh + (size_t)brow * K + k0 + lkq;
            const __nv_bfloat16* pq = Bl + (size_t)brow * K + k0 + lkq;
            uint8_t* db = sBh + lrow * LDA + lkq * 2;
            uint8_t* dq = sBl + lrow * LDA + lkq * 2;
            *(uint4*)(db +  0) = ((const uint4*)pb)[0];
            *(uint4*)(db + 16) = ((const uint4*)pb)[1];
            *(uint4*)(dq +  0) = ((const uint4*)pq)[0];
            *(uint4*)(dq + 16) = ((const uint4*)pq)[1];
        }
        __syncthreads();

#pragma unroll
        for (int kk = 0; kk < 2; kk++) {
            const uint32_t kb = kk * 32;
            uint32_t aH[2][4];
#pragma unroll
            for (int mt = 0; mt < 2; mt++) ldsm4(aH[mt], uAh + aOff + mt * 16 * LDA + kb);
            {
                uint32_t bH[4][4];
#pragma unroll
                for (int p = 0; p < 4; p++) ldsm4(bH[p], uBh + bOff + p * 16 * LDA + kb);
#pragma unroll
                for (int mt = 0; mt < 2; mt++)
#pragma unroll
                    for (int p = 0; p < 4; p++) {
                        mma16816(acc[mt][2 * p + 0], aH[mt], bH[p][0], bH[p][2]);
                        mma16816(acc[mt][2 * p + 1], aH[mt], bH[p][1], bH[p][3]);
                    }
                uint32_t aL[2][4];
#pragma unroll
                for (int mt = 0; mt < 2; mt++) ldsm4(aL[mt], uAl + aOff + mt * 16 * LDA + kb);
#pragma unroll
                for (int mt = 0; mt < 2; mt++)
#pragma unroll
                    for (int p = 0; p < 4; p++) {
                        mma16816(acc[mt][2 * p + 0], aL[mt], bH[p][0], bH[p][2]);
                        mma16816(acc[mt][2 * p + 1], aL[mt], bH[p][1], bH[p][3]);
                    }
            }
            {
                uint32_t bL[4][4];
#pragma unroll
                for (int p = 0; p < 4; p++) ldsm4(bL[p], uBl + bOff + p * 16 * LDA + kb);
#pragma unroll
                for (int mt = 0; mt < 2; mt++)
#pragma unroll
                    for (int p = 0; p < 4; p++) {
                        mma16816(acc[mt][2 * p + 0], aH[mt], bL[p][0], bL[p][2]);
                        mma16816(acc[mt][2 * p + 1], aH[mt], bL[p][1], bL[p][3]);
                    }
            }
        }
        __syncthreads();
    }

    // ---- epilogue: fp32 h + fused attention scores ----
    const int g = lane >> 2;
    const int tig = lane & 3;
    const int head = blockIdx.x * 2 + warp_n;
    const int cihb = tig * 2;

#pragma unroll
    for (int mt = 0; mt < 2; mt++) {
#pragma unroll
        for (int half = 0; half < 2; half++) {
            int grow = row0 + warp_m * 32 + mt * 16 + g + half * 8;
            if (grow >= N_NODES) continue;
            float sl = 0.f, sr = 0.f;
            float* cp = C + (size_t)grow * 256 + nbase + warp_n * 64;
#pragma unroll
            for (int nt = 0; nt < 8; nt++) {
                float c0 = acc[mt][nt][half * 2 + 0];
                float c1 = acc[mt][nt][half * 2 + 1];
                int cih = nt * 8 + cihb;
                *(float2*)(cp + cih) = make_float2(c0, c1);
                sl += c0 * alw[head * 64 + cih] + c1 * alw[head * 64 + cih + 1];
                sr += c0 * arw[head * 64 + cih] + c1 * arw[head * 64 + cih + 1];
            }
            sl += __shfl_xor_sync(0xffffffffu, sl, 1);
            sl += __shfl_xor_sync(0xffffffffu, sl, 2);
            sr += __shfl_xor_sync(0xffffffffu, sr, 1);
            sr += __shfl_xor_sync(0xffffffffu, sr, 2);
            if (tig == 0) {
                g_el[grow * 4 + head] = sl;
                g_er[grow * 4 + head] = sr;
            }
        }
    }
}

// ---------------- single-pass aggregate (no max shift; scores bounded) ----------------
template <bool LAST>
__global__ void __launch_bounds__(128) aggregate_k(const float* __restrict__ h,
                                                   float* __restrict__ out,
                                                   const float* __restrict__ Wout,
                                                   const float* __restrict__ bout, int N) {
    int v = (blockIdx.x * 128 + threadIdx.x) >> 5;
    int lane = threadIdx.x & 31;
    if (v >= N) return;
    int hd = lane >> 3;

    float4 er4 = ((const float4*)g_er)[v];
    float erv = (hd == 0) ? er4.x : (hd == 1) ? er4.y : (hd == 2) ? er4.z : er4.w;

    int r0 = g_rowptr[v];
    int r1 = g_rowptr[v + 1];

    float ssum = 0.f;
    float4 acca = make_float4(0.f, 0.f, 0.f, 0.f);
    float4 accb = make_float4(0.f, 0.f, 0.f, 0.f);

    int j = r0;
    for (; j + 2 <= r1; j += 2) {
        int s0 = g_csr_src[j];
        int s1 = g_csr_src[j + 1];
        float4 el40 = ((const float4*)g_el)[s0];
        float4 el41 = ((const float4*)g_el)[s1];
        const float4* hp0 = (const float4*)(h + (size_t)s0 * HH + lane * 8);
        const float4* hp1 = (const float4*)(h + (size_t)s1 * HH + lane * 8);
        float4 ha0 = hp0[0], hb0 = hp0[1];
        float4 ha1 = hp1[0], hb1 = hp1[1];
        float e0 = ((hd == 0) ? el40.x : (hd == 1) ? el40.y : (hd == 2) ? el40.z : el40.w) + erv;
        float e1 = ((hd == 0) ? el41.x : (hd == 1) ? el41.y : (hd == 2) ? el41.z : el41.w) + erv;
        e0 = (e0 > 0.f) ? e0 : 0.2f * e0;
        e1 = (e1 > 0.f) ? e1 : 0.2f * e1;
        float w0 = __expf(e0);
        float w1 = __expf(e1);
        ssum += w0 + w1;
        acca.x = fmaf(w0, ha0.x, fmaf(w1, ha1.x, acca.x));
        acca.y = fmaf(w0, ha0.y, fmaf(w1, ha1.y, acca.y));
        acca.z = fmaf(w0, ha0.z, fmaf(w1, ha1.z, acca.z));
        acca.w = fmaf(w0, ha0.w, fmaf(w1, ha1.w, acca.w));
        accb.x = fmaf(w0, hb0.x, fmaf(w1, hb1.x, accb.x));
        accb.y = fmaf(w0, hb0.y, fmaf(w1, hb1.y, accb.y));
        accb.z = fmaf(w0, hb0.z, fmaf(w1, hb1.z, accb.z));
        accb.w = fmaf(w0, hb0.w, fmaf(w1, hb1.w, accb.w));
    }
    if (j < r1) {
        int s0 = g_csr_src[j];
        float4 el40 = ((const float4*)g_el)[s0];
        const float4* hp0 = (const float4*)(h + (size_t)s0 * HH + lane * 8);
        float4 ha0 = hp0[0], hb0 = hp0[1];
        float e0 = ((hd == 0) ? el40.x : (hd == 1) ? el40.y : (hd == 2) ? el40.z : el40.w) + erv;
        e0 = (e0 > 0.f) ? e0 : 0.2f * e0;
        float w0 = __expf(e0);
        ssum += w0;
        acca.x = fmaf(w0, ha0.x, acca.x);
        acca.y = fmaf(w0, ha0.y, acca.y);
        acca.z = fmaf(w0, ha0.z, acca.z);
        acca.w = fmaf(w0, ha0.w, acca.w);
        accb.x = fmaf(w0, hb0.x, accb.x);
        accb.y = fmaf(w0, hb0.y, accb.y);
        accb.z = fmaf(w0, hb0.z, accb.z);
        accb.w = fmaf(w0, hb0.w, accb.w);
    }

    float inv = 1.f / (ssum + 1e-9f);
    float o[8] = {acca.x * inv, acca.y * inv, acca.z * inv, acca.w * inv,
                  accb.x * inv, accb.y * inv, accb.z * inv, accb.w * inv};
#pragma unroll
    for (int i = 0; i < 8; i++) o[i] = (o[i] > 0.f) ? o[i] : expm1f(o[i]);

    if (LAST) {
        const int dbase = (lane & 7) * 8;
        float s = 0.f;
#pragma unroll
        for (int i = 0; i < 8; i++) s += o[i] * Wout[dbase + i];
#pragma unroll
        for (int off = 16; off >= 1; off >>= 1) s += __shfl_xor_sync(0xffffffffu, s, off);
        if (lane == 0) {
            float r = 0.25f * s + bout[0];
            out[v] = (r > 0.f) ? r : 0.f;
        }
    } else {
        __nv_bfloat16 hi[8], lo[8];
#pragma unroll
        for (int i = 0; i < 8; i++) {
            hi[i] = __float2bfloat16(o[i]);
            lo[i] = __float2bfloat16(o[i] - __bfloat162float(hi[i]));
        }
        *(uint4*)(g_a_hi + (size_t)v * 256 + lane * 8) = *(const uint4*)hi;
        *(uint4*)(g_a_lo + (size_t)v * 256 + lane * 8) = *(const uint4*)lo;
    }
}

// ---------------- launch ----------------
extern "C" void kernel_launch(void* const* d_in, const int* in_sizes, int n_in,
                              void* d_out, int out_size) {
    const float* x    = (const float*)d_in[0];
    const int*   src  = (const int*)d_in[1];
    const int*   dst  = (const int*)d_in[2];
    const float* W0   = (const float*)d_in[3];
    const float* al0  = (const float*)d_in[4];
    const float* ar0  = (const float*)d_in[5];
    const float* W1   = (const float*)d_in[6];
    const float* al1  = (const float*)d_in[7];
    const float* ar1  = (const float*)d_in[8];
    const float* W2   = (const float*)d_in[9];
    const float* al2  = (const float*)d_in[10];
    const float* ar2  = (const float*)d_in[11];
    const float* Wout = (const float*)d_in[12];
    const float* bout = (const float*)d_in[13];

    const int N = N_NODES;
    const int E = N_EDGES;

    float *h;
    __nv_bfloat16 *ah, *al, *wh, *wl;
    cudaGetSymbolAddress((void**)&h, g_h);
    cudaGetSymbolAddress((void**)&ah, g_a_hi);
    cudaGetSymbolAddress((void**)&al, g_a_lo);
    cudaGetSymbolAddress((void**)&wh, g_w_hi);
    cudaGetSymbolAddress((void**)&wl, g_w_lo);

    dim3 ggrid(2, (N + 127) / 128);
    const int warpGrid = (N + 3) / 4;
    const int wtotal = 128 * 256 + 2 * 256 * 256;

    // (0) weight conversion + zero counts
    convert_w_all_k<<<(wtotal + 255) / 256, 256>>>(W0, W1, W2);
    // (1) histogram
    hist_k<<<(E + 255) / 256, 256>>>(dst, E);
    // (2) scan stage 1
    partial_k<<<NBLK, 256>>>();
    // (3) layer-0 GEMM (fp32 A, on-the-fly split) — placed at profiled slot
    gemm_mma_k<128, true><<<ggrid, 256>>>(x, nullptr, nullptr,
                                          wh + 0 * 65536, wl + 0 * 65536, h, al0, ar0);
    // (4..6) rest of CSR build
    scanpart_k<<<1, 256>>>();
    rowptr_k<<<NBLK, 256>>>();
    scatter_k<<<(E + 255) / 256, 256>>>(src, dst, E);
    // (7..) layers
    aggregate_k<false><<<warpGrid, 128>>>(h, nullptr, nullptr, nullptr, N);
    gemm_mma_k<256, false><<<ggrid, 256>>>(nullptr, ah, al,
                                           wh + 1 * 65536, wl + 1 * 65536, h, al1, ar1);
    aggregate_k<false><<<warpGrid, 128>>>(h, nullptr, nullptr, nullptr, N);
    gemm_mma_k<256, false><<<ggrid, 256>>>(nullptr, ah, al,
                                           wh + 2 * 65536, wl + 2 * 65536, h, al2, ar2);
    aggregate_k<true><<<warpGrid, 128>>>(h, (float*)d_out, Wout, bout, N);
}

// round 10
// speedup vs baseline: 1.3470x; 1.0137x over previous
#include <cuda_runtime.h>
#include <cuda_bf16.h>
#include <math.h>
#include <stdint.h>

#define N_NODES 50000
#define N_EDGES 800000
#define HH 256
#define NHEADS 4
#define MPAD 50048
#define NBLK 196          // ceil(N_NODES/256)

// ---------------- scratch ----------------
__device__ float g_h  [(size_t)N_NODES * HH];
__device__ float g_el [N_NODES * NHEADS];
__device__ float g_er [N_NODES * NHEADS];
__device__ int   g_rowptr[N_NODES + 1];
__device__ int   g_counts[N_NODES];
__device__ int   g_csr_src[N_EDGES];
__device__ int   g_part[NBLK];
__device__ int   g_partoff[NBLK];
__device__ __nv_bfloat16 g_a_hi[(size_t)MPAD * 256];
__device__ __nv_bfloat16 g_a_lo[(size_t)MPAD * 256];
__device__ __nv_bfloat16 g_w_hi[3 * 256 * 256];
__device__ __nv_bfloat16 g_w_lo[3 * 256 * 256];

// ---------------- weight conversion (+ fused count zeroing) ----------------
__global__ void convert_w_all_k(const float* __restrict__ W0,
                                const float* __restrict__ W1,
                                const float* __restrict__ W2) {
    int i = blockIdx.x * blockDim.x + threadIdx.x;
    if (i < N_NODES) g_counts[i] = 0;
    const float* W;
    __nv_bfloat16 *oh, *ol;
    int K, idx;
    if (i < 128 * 256) {
        W = W0; K = 128; idx = i;
        oh = g_w_hi + 0 * 65536; ol = g_w_lo + 0 * 65536;
    } else if (i < 128 * 256 + 256 * 256) {
        W = W1; K = 256; idx = i - 128 * 256;
        oh = g_w_hi + 1 * 65536; ol = g_w_lo + 1 * 65536;
    } else if (i < 128 * 256 + 2 * 256 * 256) {
        W = W2; K = 256; idx = i - 128 * 256 - 256 * 256;
        oh = g_w_hi + 2 * 65536; ol = g_w_lo + 2 * 65536;
    } else return;
    int k = idx / 256, n = idx % 256;
    float a = W[idx];
    __nv_bfloat16 hi = __float2bfloat16(a);
    __nv_bfloat16 lo = __float2bfloat16(a - __bfloat162float(hi));
    oh[(size_t)n * K + k] = hi;
    ol[(size_t)n * K + k] = lo;
}

// ---------------- CSR build ----------------
__global__ void hist_k(const int* __restrict__ dst, int E) {
    int i = blockIdx.x * blockDim.x + threadIdx.x;
    if (i < E) atomicAdd(&g_counts[dst[i]], 1);
}
__global__ void partial_k() {
    __shared__ int sh[256];
    int b = blockIdx.x, t = threadIdx.x;
    int i = b * 256 + t;
    sh[t] = (i < N_NODES) ? g_counts[i] : 0;
    __syncthreads();
#pragma unroll
    for (int off = 128; off >= 1; off >>= 1) {
        if (t < off) sh[t] += sh[t + off];
        __syncthreads();
    }
    if (t == 0) g_part[b] = sh[0];
}
__global__ void scanpart_k() {
    __shared__ int sh[256];
    int t = threadIdx.x;
    int v = (t < NBLK) ? g_part[t] : 0;
    sh[t] = v;
    __syncthreads();
#pragma unroll
    for (int off = 1; off < 256; off <<= 1) {
        int u = (t >= off) ? sh[t - off] : 0;
        __syncthreads();
        sh[t] += u;
        __syncthreads();
    }
    if (t < NBLK) g_partoff[t] = sh[t] - v;
    if (t == NBLK - 1) g_rowptr[N_NODES] = sh[t];
}
__global__ void rowptr_k() {
    __shared__ int sh[256];
    int b = blockIdx.x, t = threadIdx.x;
    int i = b * 256 + t;
    int v = (i < N_NODES) ? g_counts[i] : 0;
    sh[t] = v;
    __syncthreads();
#pragma unroll
    for (int off = 1; off < 256; off <<= 1) {
        int u = (t >= off) ? sh[t - off] : 0;
        __syncthreads();
        sh[t] += u;
        __syncthreads();
    }
    if (i < N_NODES) {
        g_rowptr[i] = g_partoff[b] + sh[t] - v;
        g_counts[i] = 0;
    }
}
__global__ void scatter_k(const int* __restrict__ src, const int* __restrict__ dst, int E) {
    int i = blockIdx.x * blockDim.x + threadIdx.x;
    if (i < E) {
        int d = dst[i];
        int pos = g_rowptr[d] + atomicAdd(&g_counts[d], 1);
        g_csr_src[pos] = src[i];
    }
}

// ---------------- warp-MMA helpers ----------------
__device__ __forceinline__ void ldsm4(uint32_t (&r)[4], uint32_t addr) {
    asm volatile("ldmatrix.sync.aligned.m8n8.x4.shared.b16 {%0,%1,%2,%3}, [%4];"
                 : "=r"(r[0]), "=r"(r[1]), "=r"(r[2]), "=r"(r[3]) : "r"(addr));
}
__device__ __forceinline__ void mma16816(float (&d)[4], const uint32_t (&a)[4],
                                         uint32_t b0, uint32_t b1) {
    asm volatile(
        "mma.sync.aligned.m16n8k16.row.col.f32.bf16.bf16.f32 "
        "{%0,%1,%2,%3}, {%4,%5,%6,%7}, {%8,%9}, {%0,%1,%2,%3};"
        : "+f"(d[0]), "+f"(d[1]), "+f"(d[2]), "+f"(d[3])
        : "r"(a[0]), "r"(a[1]), "r"(a[2]), "r"(a[3]), "r"(b0), "r"(b1));
}
__device__ __forceinline__ void cp16(uint32_t dst, const void* src, uint32_t n) {
    asm volatile("cp.async.cg.shared.global [%0], [%1], 16, %2;"
                 :: "r"(dst), "l"(src), "r"(n) : "memory");
}
#define CP_COMMIT() asm volatile("cp.async.commit_group;" ::: "memory")
#define CP_WAIT(n)  asm volatile("cp.async.wait_group %0;" :: "n"(n) : "memory")

#define LDA 80
#define ARR_BYTES (128 * LDA)
#define STAGE_BYTES (4 * ARR_BYTES)   // 40960
#define DB_SMEM (2 * STAGE_BYTES)     // 81920

// ===== shared epilogue: write C + fused el/er =====
__device__ __forceinline__ void gemm_epilogue(
    float (&acc)[2][8][4], float* __restrict__ C,
    const float* __restrict__ alw, const float* __restrict__ arw,
    int row0, int nbase, int warp_m, int warp_n, int lane)
{
    const int g = lane >> 2;
    const int tig = lane & 3;
    const int head = (nbase >> 6) + warp_n;
    const int cihb = tig * 2;
#pragma unroll
    for (int mt = 0; mt < 2; mt++) {
#pragma unroll
        for (int half = 0; half < 2; half++) {
            int grow = row0 + warp_m * 32 + mt * 16 + g + half * 8;
            if (grow >= N_NODES) continue;
            float sl = 0.f, sr = 0.f;
            float* cp = C + (size_t)grow * 256 + nbase + warp_n * 64;
#pragma unroll
            for (int nt = 0; nt < 8; nt++) {
                float c0 = acc[mt][nt][half * 2 + 0];
                float c1 = acc[mt][nt][half * 2 + 1];
                int cih = nt * 8 + cihb;
                *(float2*)(cp + cih) = make_float2(c0, c1);
                sl += c0 * alw[head * 64 + cih] + c1 * alw[head * 64 + cih + 1];
                sr += c0 * arw[head * 64 + cih] + c1 * arw[head * 64 + cih + 1];
            }
            sl += __shfl_xor_sync(0xffffffffu, sl, 1);
            sl += __shfl_xor_sync(0xffffffffu, sl, 2);
            sr += __shfl_xor_sync(0xffffffffu, sr, 1);
            sr += __shfl_xor_sync(0xffffffffu, sr, 2);
            if (tig == 0) {
                g_el[grow * 4 + head] = sl;
                g_er[grow * 4 + head] = sr;
            }
        }
    }
}

// ===== shared compute for one staged 32-K chunk =====
__device__ __forceinline__ void gemm_chunk_compute(
    float (&acc)[2][8][4], uint32_t uAh, uint32_t uAl, uint32_t uBh, uint32_t uBl,
    uint32_t aOff, uint32_t bOff)
{
#pragma unroll
    for (int kk = 0; kk < 2; kk++) {
        const uint32_t kb = kk * 32;
        uint32_t aH[2][4];
#pragma unroll
        for (int mt = 0; mt < 2; mt++) ldsm4(aH[mt], uAh + aOff + mt * 16 * LDA + kb);
        {
            uint32_t bH[4][4];
#pragma unroll
            for (int p = 0; p < 4; p++) ldsm4(bH[p], uBh + bOff + p * 16 * LDA + kb);
#pragma unroll
            for (int mt = 0; mt < 2; mt++)
#pragma unroll
                for (int p = 0; p < 4; p++) {
                    mma16816(acc[mt][2 * p + 0], aH[mt], bH[p][0], bH[p][2]);
                    mma16816(acc[mt][2 * p + 1], aH[mt], bH[p][1], bH[p][3]);
                }
            uint32_t aL[2][4];
#pragma unroll
            for (int mt = 0; mt < 2; mt++) ldsm4(aL[mt], uAl + aOff + mt * 16 * LDA + kb);
#pragma unroll
            for (int mt = 0; mt < 2; mt++)
#pragma unroll
                for (int p = 0; p < 4; p++) {
                    mma16816(acc[mt][2 * p + 0], aL[mt], bH[p][0], bH[p][2]);
                    mma16816(acc[mt][2 * p + 1], aL[mt], bH[p][1], bH[p][3]);
                }
        }
        {
            uint32_t bL[4][4];
#pragma unroll
            for (int p = 0; p < 4; p++) ldsm4(bL[p], uBl + bOff + p * 16 * LDA + kb);
#pragma unroll
            for (int mt = 0; mt < 2; mt++)
#pragma unroll
                for (int p = 0; p < 4; p++) {
                    mma16816(acc[mt][2 * p + 0], aH[mt], bL[p][0], bL[p][2]);
                    mma16816(acc[mt][2 * p + 1], aH[mt], bL[p][1], bL[p][3]);
                }
        }
    }
}

// ---------------- layer-0 GEMM: fp32 A with on-the-fly split (single buffer) ----------------
__global__ void __launch_bounds__(256, 2) gemm_l0_k(
    const float* __restrict__ Afp,
    const __nv_bfloat16* __restrict__ Bh, const __nv_bfloat16* __restrict__ Bl,
    float* __restrict__ C, const float* __restrict__ alw, const float* __restrict__ arw)
{
    constexpr int K = 128;
    __shared__ __align__(16) uint8_t sAh[128 * LDA];
    __shared__ __align__(16) uint8_t sAl[128 * LDA];
    __shared__ __align__(16) uint8_t sBh[128 * LDA];
    __shared__ __align__(16) uint8_t sBl[128 * LDA];

    const int t = threadIdx.x;
    const int wid = t >> 5, lane = t & 31;
    const int warp_m = wid & 3, warp_n = wid >> 2;
    const int row0 = blockIdx.y * 128;
    const int nbase = blockIdx.x * 128;

    float acc[2][8][4];
#pragma unroll
    for (int i = 0; i < 2; i++)
#pragma unroll
        for (int j = 0; j < 8; j++)
#pragma unroll
            for (int q = 0; q < 4; q++) acc[i][j][q] = 0.f;

    const uint32_t uAh = (uint32_t)__cvta_generic_to_shared(sAh);
    const uint32_t uAl = (uint32_t)__cvta_generic_to_shared(sAl);
    const uint32_t uBh = (uint32_t)__cvta_generic_to_shared(sBh);
    const uint32_t uBl = (uint32_t)__cvta_generic_to_shared(sBl);
    const uint32_t rowOff = (uint32_t)(lane & 15) * LDA + (uint32_t)((lane >> 4) << 4);
    const uint32_t aOff = (uint32_t)warp_m * 32 * LDA + rowOff;
    const uint32_t bOff = (uint32_t)warp_n * 64 * LDA + rowOff;

    const int lrow = t >> 1;
    const int lkq = (t & 1) * 16;
    const int arow = row0 + lrow;
    const bool aok = arow < N_NODES;
    const int brow = nbase + lrow;

    for (int k0 = 0; k0 < K; k0 += 32) {
        {
            uint8_t* da = sAh + lrow * LDA + lkq * 2;
            uint8_t* dl = sAl + lrow * LDA + lkq * 2;
            const float* pa32 = Afp + (size_t)arow * K + k0 + lkq;
            float f[16];
#pragma unroll
            for (int q = 0; q < 4; q++) {
                float4 v = aok ? ((const float4*)pa32)[q] : make_float4(0.f, 0.f, 0.f, 0.f);
                f[q * 4 + 0] = v.x; f[q * 4 + 1] = v.y;
                f[q * 4 + 2] = v.z; f[q * 4 + 3] = v.w;
            }
            __nv_bfloat16 hi[16], lo[16];
#pragma unroll
            for (int q = 0; q < 16; q++) {
                hi[q] = __float2bfloat16(f[q]);
                lo[q] = __float2bfloat16(f[q] - __bfloat162float(hi[q]));
            }
            *(uint4*)(da +  0) = ((const uint4*)hi)[0];
            *(uint4*)(da + 16) = ((const uint4*)hi)[1];
            *(uint4*)(dl +  0) = ((const uint4*)lo)[0];
            *(uint4*)(dl + 16) = ((const uint4*)lo)[1];

            const __nv_bfloat16* pb = Bh + (size_t)brow * K + k0 + lkq;
            const __nv_bfloat16* pq = Bl + (size_t)brow * K + k0 + lkq;
            uint8_t* db = sBh + lrow * LDA + lkq * 2;
            uint8_t* dq = sBl + lrow * LDA + lkq * 2;
            *(uint4*)(db +  0) = ((const uint4*)pb)[0];
            *(uint4*)(db + 16) = ((const uint4*)pb)[1];
            *(uint4*)(dq +  0) = ((const uint4*)pq)[0];
            *(uint4*)(dq + 16) = ((const uint4*)pq)[1];
        }
        __syncthreads();
        gemm_chunk_compute(acc, uAh, uAl, uBh, uBl, aOff, bOff);
        __syncthreads();
    }
    gemm_epilogue(acc, C, alw, arw, row0, nbase, warp_m, warp_n, lane);
}

// ---------------- layers 1-2 GEMM: bf16 operands, cp.async double buffer ----------------
__global__ void __launch_bounds__(256, 2) gemm_db_k(
    const __nv_bfloat16* __restrict__ Ah, const __nv_bfloat16* __restrict__ Al,
    const __nv_bfloat16* __restrict__ Bh, const __nv_bfloat16* __restrict__ Bl,
    float* __restrict__ C, const float* __restrict__ alw, const float* __restrict__ arw)
{
    constexpr int K = 256;
    constexpr int NCHUNK = K / 32;
    extern __shared__ __align__(16) uint8_t smem[];

    const int t = threadIdx.x;
    const int wid = t >> 5, lane = t & 31;
    const int warp_m = wid & 3, warp_n = wid >> 2;
    const int row0 = blockIdx.y * 128;
    const int nbase = blockIdx.x * 128;

    float acc[2][8][4];
#pragma unroll
    for (int i = 0; i < 2; i++)
#pragma unroll
        for (int j = 0; j < 8; j++)
#pragma unroll
            for (int q = 0; q < 4; q++) acc[i][j][q] = 0.f;

    const uint32_t sbase = (uint32_t)__cvta_generic_to_shared(smem);
    const uint32_t rowOff = (uint32_t)(lane & 15) * LDA + (uint32_t)((lane >> 4) << 4);
    const uint32_t aOff = (uint32_t)warp_m * 32 * LDA + rowOff;
    const uint32_t bOff = (uint32_t)warp_n * 64 * LDA + rowOff;

    const int lrow = t >> 1;
    const int lhalf = (t & 1) * 32;
    const int arow_real = row0 + lrow;
    const bool aok = arow_real < N_NODES;
    const int arow = aok ? arow_real : (N_NODES - 1);
    const uint32_t asz = aok ? 16u : 0u;
    const int brow = nbase + lrow;
    const uint32_t dOff = (uint32_t)lrow * LDA + (uint32_t)lhalf;

    auto issue = [&](int c, int stage) {
        const int k0 = c * 32;
        const uint32_t sb = sbase + stage * STAGE_BYTES + dOff;
        const char* pa = (const char*)(Ah + (size_t)arow * K + k0) + lhalf;
        const char* pl = (const char*)(Al + (size_t)arow * K + k0) + lhalf;
        const char* pb = (const char*)(Bh + (size_t)brow * K + k0) + lhalf;
        const char* pq = (const char*)(Bl + (size_t)brow * K + k0) + lhalf;
        cp16(sb + 0 * ARR_BYTES +  0, pa +  0, asz);
        cp16(sb + 0 * ARR_BYTES + 16, pa + 16, asz);
        cp16(sb + 1 * ARR_BYTES +  0, pl +  0, asz);
        cp16(sb + 1 * ARR_BYTES + 16, pl + 16, asz);
        cp16(sb + 2 * ARR_BYTES +  0, pb +  0, 16u);
        cp16(sb + 2 * ARR_BYTES + 16, pb + 16, 16u);
        cp16(sb + 3 * ARR_BYTES +  0, pq +  0, 16u);
        cp16(sb + 3 * ARR_BYTES + 16, pq + 16, 16u);
        CP_COMMIT();
    };

    issue(0, 0);
    for (int c = 0; c < NCHUNK; c++) {
        const int stage = c & 1;
        if (c + 1 < NCHUNK) {
            issue(c + 1, stage ^ 1);
            CP_WAIT(1);
        } else {
            CP_WAIT(0);
        }
        __syncthreads();
        const uint32_t uAh = sbase + stage * STAGE_BYTES;
        gemm_chunk_compute(acc, uAh, uAh + ARR_BYTES, uAh + 2 * ARR_BYTES,
                           uAh + 3 * ARR_BYTES, aOff, bOff);
        __syncthreads();
    }
    gemm_epilogue(acc, C, alw, arw, row0, nbase, warp_m, warp_n, lane);
}

// ---------------- single-pass aggregate ----------------
template <bool LAST>
__global__ void __launch_bounds__(128) aggregate_k(const float* __restrict__ h,
                                                   float* __restrict__ out,
                                                   const float* __restrict__ Wout,
                                                   const float* __restrict__ bout, int N) {
    int v = (blockIdx.x * 128 + threadIdx.x) >> 5;
    int lane = threadIdx.x & 31;
    if (v >= N) return;
    int hd = lane >> 3;

    float4 er4 = ((const float4*)g_er)[v];
    float erv = (hd == 0) ? er4.x : (hd == 1) ? er4.y : (hd == 2) ? er4.z : er4.w;

    int r0 = g_rowptr[v];
    int r1 = g_rowptr[v + 1];

    float ssum = 0.f;
    float4 acca = make_float4(0.f, 0.f, 0.f, 0.f);
    float4 accb = make_float4(0.f, 0.f, 0.f, 0.f);

    int j = r0;
    for (; j + 2 <= r1; j += 2) {
        int s0 = g_csr_src[j];
        int s1 = g_csr_src[j + 1];
        float4 el40 = ((const float4*)g_el)[s0];
        float4 el41 = ((const float4*)g_el)[s1];
        const float4* hp0 = (const float4*)(h + (size_t)s0 * HH + lane * 8);
        const float4* hp1 = (const float4*)(h + (size_t)s1 * HH + lane * 8);
        float4 ha0 = hp0[0], hb0 = hp0[1];
        float4 ha1 = hp1[0], hb1 = hp1[1];
        float e0 = ((hd == 0) ? el40.x : (hd == 1) ? el40.y : (hd == 2) ? el40.z : el40.w) + erv;
        float e1 = ((hd == 0) ? el41.x : (hd == 1) ? el41.y : (hd == 2) ? el41.z : el41.w) + erv;
        e0 = (e0 > 0.f) ? e0 : 0.2f * e0;
        e1 = (e1 > 0.f) ? e1 : 0.2f * e1;
        float w0 = __expf(e0);
        float w1 = __expf(e1);
        ssum += w0 + w1;
        acca.x = fmaf(w0, ha0.x, fmaf(w1, ha1.x, acca.x));
        acca.y = fmaf(w0, ha0.y, fmaf(w1, ha1.y, acca.y));
        acca.z = fmaf(w0, ha0.z, fmaf(w1, ha1.z, acca.z));
        acca.w = fmaf(w0, ha0.w, fmaf(w1, ha1.w, acca.w));
        accb.x = fmaf(w0, hb0.x, fmaf(w1, hb1.x, accb.x));
        accb.y = fmaf(w0, hb0.y, fmaf(w1, hb1.y, accb.y));
        accb.z = fmaf(w0, hb0.z, fmaf(w1, hb1.z, accb.z));
        accb.w = fmaf(w0, hb0.w, fmaf(w1, hb1.w, accb.w));
    }
    if (j < r1) {
        int s0 = g_csr_src[j];
        float4 el40 = ((const float4*)g_el)[s0];
        const float4* hp0 = (const float4*)(h + (size_t)s0 * HH + lane * 8);
        float4 ha0 = hp0[0], hb0 = hp0[1];
        float e0 = ((hd == 0) ? el40.x : (hd == 1) ? el40.y : (hd == 2) ? el40.z : el40.w) + erv;
        e0 = (e0 > 0.f) ? e0 : 0.2f * e0;
        float w0 = __expf(e0);
        ssum += w0;
        acca.x = fmaf(w0, ha0.x, acca.x);
        acca.y = fmaf(w0, ha0.y, acca.y);
        acca.z = fmaf(w0, ha0.z, acca.z);
        acca.w = fmaf(w0, ha0.w, acca.w);
        accb.x = fmaf(w0, hb0.x, accb.x);
        accb.y = fmaf(w0, hb0.y, accb.y);
        accb.z = fmaf(w0, hb0.z, accb.z);
        accb.w = fmaf(w0, hb0.w, accb.w);
    }

    float inv = 1.f / (ssum + 1e-9f);
    float o[8] = {acca.x * inv, acca.y * inv, acca.z * inv, acca.w * inv,
                  accb.x * inv, accb.y * inv, accb.z * inv, accb.w * inv};
#pragma unroll
    for (int i = 0; i < 8; i++) o[i] = (o[i] > 0.f) ? o[i] : expm1f(o[i]);

    if (LAST) {
        const int dbase = (lane & 7) * 8;
        float s = 0.f;
#pragma unroll
        for (int i = 0; i < 8; i++) s += o[i] * Wout[dbase + i];
#pragma unroll
        for (int off = 16; off >= 1; off >>= 1) s += __shfl_xor_sync(0xffffffffu, s, off);
        if (lane == 0) {
            float r = 0.25f * s + bout[0];
            out[v] = (r > 0.f) ? r : 0.f;
        }
    } else {
        __nv_bfloat16 hi[8], lo[8];
#pragma unroll
        for (int i = 0; i < 8; i++) {
            hi[i] = __float2bfloat16(o[i]);
            lo[i] = __float2bfloat16(o[i] - __bfloat162float(hi[i]));
        }
        *(uint4*)(g_a_hi + (size_t)v * 256 + lane * 8) = *(const uint4*)hi;
        *(uint4*)(g_a_lo + (size_t)v * 256 + lane * 8) = *(const uint4*)lo;
    }
}

// ---------------- launch ----------------
extern "C" void kernel_launch(void* const* d_in, const int* in_sizes, int n_in,
                              void* d_out, int out_size) {
    const float* x    = (const float*)d_in[0];
    const int*   src  = (const int*)d_in[1];
    const int*   dst  = (const int*)d_in[2];
    const float* W0   = (const float*)d_in[3];
    const float* al0  = (const float*)d_in[4];
    const float* ar0  = (const float*)d_in[5];
    const float* W1   = (const float*)d_in[6];
    const float* al1  = (const float*)d_in[7];
    const float* ar1  = (const float*)d_in[8];
    const float* W2   = (const float*)d_in[9];
    const float* al2  = (const float*)d_in[10];
    const float* ar2  = (const float*)d_in[11];
    const float* Wout = (const float*)d_in[12];
    const float* bout = (const float*)d_in[13];

    const int N = N_NODES;
    const int E = N_EDGES;

    float *h;
    __nv_bfloat16 *ah, *al, *wh, *wl;
    cudaGetSymbolAddress((void**)&h, g_h);
    cudaGetSymbolAddress((void**)&ah, g_a_hi);
    cudaGetSymbolAddress((void**)&al, g_a_lo);
    cudaGetSymbolAddress((void**)&wh, g_w_hi);
    cudaGetSymbolAddress((void**)&wl, g_w_lo);

    cudaFuncSetAttribute(gemm_db_k, cudaFuncAttributeMaxDynamicSharedMemorySize, DB_SMEM);

    dim3 ggrid(2, (N + 127) / 128);
    const int warpGrid = (N + 3) / 4;
    const int wtotal = 128 * 256 + 2 * 256 * 256;

    convert_w_all_k<<<(wtotal + 255) / 256, 256>>>(W0, W1, W2);
    hist_k<<<(E + 255) / 256, 256>>>(dst, E);
    partial_k<<<NBLK, 256>>>();
    // slot 3 (profiled): layer-0 GEMM — control for this round
    gemm_l0_k<<<ggrid, 256>>>(x, wh + 0 * 65536, wl + 0 * 65536, h, al0, ar0);
    scanpart_k<<<1, 256>>>();
    rowptr_k<<<NBLK, 256>>>();
    scatter_k<<<(E + 255) / 256, 256>>>(src, dst, E);
    aggregate_k<false><<<warpGrid, 128>>>(h, nullptr, nullptr, nullptr, N);
    gemm_db_k<<<ggrid, 256, DB_SMEM>>>(ah, al, wh + 1 * 65536, wl + 1 * 65536, h, al1, ar1);
    aggregate_k<false><<<warpGrid, 128>>>(h, nullptr, nullptr, nullptr, N);
    gemm_db_k<<<ggrid, 256, DB_SMEM>>>(ah, al, wh + 2 * 65536, wl + 2 * 65536, h, al2, ar2);
    aggregate_k<true><<<warpGrid, 128>>>(h, (float*)d_out, Wout, bout, N);
}